// round 2
// baseline (speedup 1.0000x reference)
#include <cuda_runtime.h>
#include <math.h>

// Problem constants (fixed by the dataset)
#define IN_DIM   1024
#define OUT_DIM  1024
#define HID_DIM  2048
#define L_DIM    4096
#define B_DIM    1024
#define NCOLS    3072          // L - IN : only columns [IN, L) are ever computed
#define NSTEPS   32
#define EPS_N    1e-12f

// Static device scratch (allocation-free per harness rules)
// g_mw rows are (outputCol - IN), K-contiguous:  g_mw[(i-IN)*L + j] = W[i][j] * A[j][i]
__device__ float g_mw[(size_t)NCOLS * L_DIM];       // 48 MB
__device__ float g_buf1[(size_t)B_DIM * L_DIM];     // 16 MB ping-pong buffer

// ---------------------------------------------------------------------------
// Precompute masked weights mw = W * A^T for rows [IN, L).
// 32x32 transpose tile so both W (row-major along j) and A (row-major along i)
// reads are coalesced.
// ---------------------------------------------------------------------------
__global__ void prep_mw_kernel(const float* __restrict__ W,
                               const float* __restrict__ A) {
    __shared__ float tile[32][33];
    const int i0 = blockIdx.y * 32;      // mw row block (0..NCOLS)
    const int j0 = blockIdx.x * 32;      // column block (0..L)
    const int tx = threadIdx.x, ty = threadIdx.y;

    // coalesced read of A[j][IN + i]:  j = j0+ty (row), i = i0+tx (col)
    tile[ty][tx] = A[(size_t)(j0 + ty) * L_DIM + (IN_DIM + i0 + tx)];
    __syncthreads();

    const int i = i0 + ty;               // mw row
    const int j = j0 + tx;               // mw col
    // coalesced read of W[IN+i][j] along tx, coalesced write of g_mw
    g_mw[(size_t)i * L_DIM + j] =
        W[(size_t)(IN_DIM + i) * L_DIM + j] * tile[tx][ty];
}

// ---------------------------------------------------------------------------
// Initialize: buf0(=d_out) = [x | 0 | 0]; buf1 cols [0,IN) = x (x-cols are
// constant across all steps so they are written exactly once per buffer).
// ---------------------------------------------------------------------------
__global__ void init_kernel(const float* __restrict__ x,
                            float* __restrict__ buf0) {
    size_t idx = (size_t)blockIdx.x * blockDim.x + threadIdx.x;
    if (idx >= (size_t)B_DIM * L_DIM) return;
    int col = (int)(idx % L_DIM);
    int row = (int)(idx / L_DIM);
    float v = 0.0f;
    if (col < IN_DIM) {
        v = x[(size_t)row * IN_DIM + col];
        g_buf1[idx] = v;                 // x-columns of the scratch buffer
    }
    buf0[idx] = v;
}

// ---------------------------------------------------------------------------
// GEMM + relu:  dst[b, IN+n] = relu( sum_j src[b,j] * g_mw[n, j] )
// C(M=1024, N=3072, K=4096). Both operands K-contiguous ("NT" layout).
// BM=BN=128, BK=8, 256 threads, 8x8 register micro-tile.
// step parity selects src/dst between d_out (bufA) and g_buf1.
// ---------------------------------------------------------------------------
__global__ __launch_bounds__(256, 2)
void gemm_relu_kernel(float* __restrict__ bufA, int step) {
    const int BM = 128, BN = 128, BK = 8, TM = 8, TN = 8;
    __shared__ float As[BK][BM];
    __shared__ float Bs[BK][BN];

    const float* __restrict__ src = ((step & 1) == 0) ? bufA : g_buf1;
    float*       __restrict__ dst = ((step & 1) == 0) ? g_buf1 : bufA;

    const int tid = threadIdx.x;
    const int bx = blockIdx.x;           // N tile: 0..23
    const int by = blockIdx.y;           // M tile: 0..7

    const int threadCol = tid % 16;      // 16x16 thread grid
    const int threadRow = tid / 16;

    // cooperative load indices: 256 threads x float4 covers a 128x8 tile
    const int ldRow = tid >> 1;          // 0..127
    const int ldCol = (tid & 1) * 4;     // 0 or 4

    const float* Abase = src  + (size_t)by * BM * L_DIM + (size_t)ldRow * L_DIM + ldCol;
    const float* Bbase = g_mw + (size_t)bx * BN * L_DIM + (size_t)ldRow * L_DIM + ldCol;

    float acc[TM][TN];
    #pragma unroll
    for (int i = 0; i < TM; i++)
        #pragma unroll
        for (int j = 0; j < TN; j++) acc[i][j] = 0.0f;

    for (int kt = 0; kt < L_DIM; kt += BK) {
        // load + transpose into smem
        float4 a4 = *reinterpret_cast<const float4*>(Abase + kt);
        float4 b4 = *reinterpret_cast<const float4*>(Bbase + kt);
        As[ldCol + 0][ldRow] = a4.x;
        As[ldCol + 1][ldRow] = a4.y;
        As[ldCol + 2][ldRow] = a4.z;
        As[ldCol + 3][ldRow] = a4.w;
        Bs[ldCol + 0][ldRow] = b4.x;
        Bs[ldCol + 1][ldRow] = b4.y;
        Bs[ldCol + 2][ldRow] = b4.z;
        Bs[ldCol + 3][ldRow] = b4.w;
        __syncthreads();

        #pragma unroll
        for (int k = 0; k < BK; k++) {
            float regM[TM], regN[TN];
            float4 m0 = *reinterpret_cast<const float4*>(&As[k][threadRow * TM]);
            float4 m1 = *reinterpret_cast<const float4*>(&As[k][threadRow * TM + 4]);
            float4 n0 = *reinterpret_cast<const float4*>(&Bs[k][threadCol * TN]);
            float4 n1 = *reinterpret_cast<const float4*>(&Bs[k][threadCol * TN + 4]);
            regM[0]=m0.x; regM[1]=m0.y; regM[2]=m0.z; regM[3]=m0.w;
            regM[4]=m1.x; regM[5]=m1.y; regM[6]=m1.z; regM[7]=m1.w;
            regN[0]=n0.x; regN[1]=n0.y; regN[2]=n0.z; regN[3]=n0.w;
            regN[4]=n1.x; regN[5]=n1.y; regN[6]=n1.z; regN[7]=n1.w;
            #pragma unroll
            for (int i = 0; i < TM; i++)
                #pragma unroll
                for (int j = 0; j < TN; j++)
                    acc[i][j] += regM[i] * regN[j];
        }
        __syncthreads();
    }

    // epilogue: relu + vectorized store into columns [IN, L)
    #pragma unroll
    for (int i = 0; i < TM; i++) {
        const int row = by * BM + threadRow * TM + i;
        float* drow = dst + (size_t)row * L_DIM + IN_DIM + bx * BN + threadCol * TN;
        #pragma unroll
        for (int j = 0; j < TN; j += 4) {
            float4 v;
            v.x = fmaxf(acc[i][j + 0], 0.0f);
            v.y = fmaxf(acc[i][j + 1], 0.0f);
            v.z = fmaxf(acc[i][j + 2], 0.0f);
            v.w = fmaxf(acc[i][j + 3], 0.0f);
            *reinterpret_cast<float4*>(drow + j) = v;
        }
    }
}

// ---------------------------------------------------------------------------
// Row-normalize the HID slice of dst: hid /= max(||hid||, EPS).
// One block per batch row; 256 threads; float4 vectorized.
// ---------------------------------------------------------------------------
__global__ __launch_bounds__(256)
void norm_hid_kernel(float* __restrict__ bufA, int step) {
    float* dst = ((step & 1) == 0) ? g_buf1 : bufA;
    const int row = blockIdx.x;
    float4* hid = reinterpret_cast<float4*>(dst + (size_t)row * L_DIM + IN_DIM + OUT_DIM);

    const int tid = threadIdx.x;
    float ss = 0.0f;
    float4 v0 = hid[tid];
    float4 v1 = hid[tid + 256];
    ss += v0.x * v0.x + v0.y * v0.y + v0.z * v0.z + v0.w * v0.w;
    ss += v1.x * v1.x + v1.y * v1.y + v1.z * v1.z + v1.w * v1.w;

    // block reduce: 8 warps
    __shared__ float red[8];
    __shared__ float s_scale;
    #pragma unroll
    for (int off = 16; off > 0; off >>= 1)
        ss += __shfl_xor_sync(0xFFFFFFFFu, ss, off);
    if ((tid & 31) == 0) red[tid >> 5] = ss;
    __syncthreads();
    if (tid == 0) {
        float t = 0.0f;
        #pragma unroll
        for (int w = 0; w < 8; w++) t += red[w];
        s_scale = 1.0f / fmaxf(sqrtf(t), EPS_N);
    }
    __syncthreads();
    const float sc = s_scale;

    v0.x *= sc; v0.y *= sc; v0.z *= sc; v0.w *= sc;
    v1.x *= sc; v1.y *= sc; v1.z *= sc; v1.w *= sc;
    hid[tid] = v0;
    hid[tid + 256] = v1;
}

// ---------------------------------------------------------------------------
// kernel_launch: inputs per metadata order: x, y, W, A, n.
// n is fixed at 32 by the dataset (cannot be read host-side under capture).
// ---------------------------------------------------------------------------
extern "C" void kernel_launch(void* const* d_in, const int* in_sizes, int n_in,
                              void* d_out, int out_size) {
    const float* x = (const float*)d_in[0];
    const float* W = (const float*)d_in[2];
    const float* A = (const float*)d_in[3];
    float* out = (float*)d_out;          // acts as ping-pong buffer 0

    // 1) mw = (W * A^T) rows [IN, L)
    {
        dim3 blk(32, 32);
        dim3 grd(L_DIM / 32, NCOLS / 32);
        prep_mw_kernel<<<grd, blk>>>(W, A);
    }

    // 2) init act0 into buf0(=d_out); x-cols into buf1
    {
        size_t total = (size_t)B_DIM * L_DIM;
        init_kernel<<<(unsigned)((total + 255) / 256), 256>>>(x, out);
    }

    // 3) 32 iterations: GEMM+relu then hid normalize.
    //    step even: src=d_out  -> dst=g_buf1
    //    step odd : src=g_buf1 -> dst=d_out
    //    After 32 steps (last step = 31, odd) result lands in d_out.
    dim3 gblk(256);
    dim3 ggrd(NCOLS / 128, B_DIM / 128);  // 24 x 8
    for (int s = 0; s < NSTEPS; s++) {
        gemm_relu_kernel<<<ggrd, gblk>>>(out, s);
        norm_hid_kernel<<<B_DIM, 256>>>(out, s);
    }
}

// round 4
// speedup vs baseline: 4.2089x; 4.2089x over previous
#include <cuda_runtime.h>
#include <cuda_bf16.h>
#include <stdint.h>
#include <math.h>

// ---------------------------------------------------------------- constants
#define IN_DIM   1024
#define OUT_DIM  1024
#define HID_DIM  2048
#define L_DIM    4096
#define B_DIM    1024
#define NCOLS    3072
#define NSTEPS   32
#define EPS_N    1e-12f

// GEMM: C(M=1024, N=3072, K=4096). CTA tile 128x192, K-chunk 32.
#define MT       128
#define NT       192
#define KC       32
#define NKC      128            // 4096/32
#define MTILES   8
#define NTILES   16             // grid 16x8 = 128 CTAs (one wave on 148 SMs)

#define ROWB     64             // bytes per smem row (32 bf16)
#define STG_A    (MT*ROWB)      // 8192
#define STG_B    (NT*ROWB)      // 12288
#define STAGE    (2*STG_A + 2*STG_B)   // 40960
#define NSTAGES  4
#define SMEM_TOT (NSTAGES*STAGE)        // 163840

#define ACT_ELEMS ((size_t)B_DIM * L_DIM)   // 4M

// ---------------------------------------------------------------- device scratch
__device__ __align__(1024) __nv_bfloat16 g_wt_hi[(size_t)NCOLS * L_DIM];   // 24 MB
__device__ __align__(1024) __nv_bfloat16 g_wt_lo[(size_t)NCOLS * L_DIM];   // 24 MB
__device__ __align__(1024) __nv_bfloat16 g_act_hi[2 * ACT_ELEMS];          // 16 MB
__device__ __align__(1024) __nv_bfloat16 g_act_lo[2 * ACT_ELEMS];          // 16 MB

// ---------------------------------------------------------------- helpers
__device__ __forceinline__ uint32_t swz64(uint32_t b) { return b ^ ((b >> 3) & 0x30u); }

__device__ __forceinline__ uint32_t s2u(const void* p) {
    uint32_t a;
    asm("{ .reg .u64 t; cvta.to.shared.u64 t, %1; cvt.u32.u64 %0, t; }" : "=r"(a) : "l"(p));
    return a;
}
__device__ __forceinline__ void cp16(uint32_t dst, const void* src) {
    asm volatile("cp.async.cg.shared.global [%0], [%1], 16;" :: "r"(dst), "l"(src));
}
__device__ __forceinline__ void cp_commit() { asm volatile("cp.async.commit_group;"); }
template <int N>
__device__ __forceinline__ void cp_wait() { asm volatile("cp.async.wait_group %0;" :: "n"(N)); }

__device__ __forceinline__ void ldsm4(uint32_t* r, uint32_t addr) {
    asm volatile("ldmatrix.sync.aligned.m8n8.x4.shared.b16 {%0,%1,%2,%3}, [%4];"
                 : "=r"(r[0]), "=r"(r[1]), "=r"(r[2]), "=r"(r[3]) : "r"(addr));
}
__device__ __forceinline__ void mma16816(float* c, const uint32_t* a, const uint32_t* b) {
    asm volatile("mma.sync.aligned.m16n8k16.row.col.f32.bf16.bf16.f32 "
                 "{%0,%1,%2,%3}, {%4,%5,%6,%7}, {%8,%9}, {%0,%1,%2,%3};"
                 : "+f"(c[0]), "+f"(c[1]), "+f"(c[2]), "+f"(c[3])
                 : "r"(a[0]), "r"(a[1]), "r"(a[2]), "r"(a[3]), "r"(b[0]), "r"(b[1]));
}

__device__ __forceinline__ void split2(float f0, float f1, uint32_t& H, uint32_t& L) {
    __nv_bfloat16 h0 = __float2bfloat16_rn(f0);
    __nv_bfloat16 h1 = __float2bfloat16_rn(f1);
    __nv_bfloat16 l0 = __float2bfloat16_rn(f0 - __bfloat162float(h0));
    __nv_bfloat16 l1 = __float2bfloat16_rn(f1 - __bfloat162float(h1));
    H = (uint32_t)__bfloat16_as_ushort(h0) | ((uint32_t)__bfloat16_as_ushort(h1) << 16);
    L = (uint32_t)__bfloat16_as_ushort(l0) | ((uint32_t)__bfloat16_as_ushort(l1) << 16);
}
__device__ __forceinline__ void split8(const float* f, uint4& H, uint4& L) {
    uint32_t hw[4], lw[4];
    #pragma unroll
    for (int p = 0; p < 4; p++) split2(f[2*p], f[2*p+1], hw[p], lw[p]);
    H = make_uint4(hw[0], hw[1], hw[2], hw[3]);
    L = make_uint4(lw[0], lw[1], lw[2], lw[3]);
}

// ---------------------------------------------------------------- prep weights
// mw[i][j] = W[IN+i][j] * A[j][IN+i]  (i in [0,3072)), bf16 hi/lo row-major.
__global__ void prep_w(const float* __restrict__ W, const float* __restrict__ A) {
    __shared__ float tile[32][33];
    const int i0 = blockIdx.y * 32, j0 = blockIdx.x * 32;
    const int tx = threadIdx.x, ty = threadIdx.y;
    tile[ty][tx] = A[(size_t)(j0 + ty) * L_DIM + (IN_DIM + i0 + tx)];
    __syncthreads();
    const int i = i0 + ty, j = j0 + tx;
    float v = W[(size_t)(IN_DIM + i) * L_DIM + j] * tile[tx][ty];
    __nv_bfloat16 h = __float2bfloat16_rn(v);
    __nv_bfloat16 l = __float2bfloat16_rn(v - __bfloat162float(h));
    g_wt_hi[(size_t)i * L_DIM + j] = h;
    g_wt_lo[(size_t)i * L_DIM + j] = l;
}

// ---------------------------------------------------------------- init activations
// dout x-cols = x (fp32). act buffers (row-major bf16 hi/lo):
//   x cols -> both buffers; remaining cols of buffer 0 -> zero.
__global__ void init_act(const float* __restrict__ x, float* __restrict__ dout) {
    int g = blockIdx.x * blockDim.x + threadIdx.x;   // 1024 rows * 512 groups of 8
    int row = g >> 9;
    int k0 = (g & 511) * 8;
    size_t off = (size_t)row * L_DIM + k0;
    if (k0 < IN_DIM) {
        float4 a = *(const float4*)(x + (size_t)row * IN_DIM + k0);
        float4 b = *(const float4*)(x + (size_t)row * IN_DIM + k0 + 4);
        *(float4*)(dout + off)     = a;
        *(float4*)(dout + off + 4) = b;
        float f[8] = {a.x, a.y, a.z, a.w, b.x, b.y, b.z, b.w};
        uint4 H, L;
        split8(f, H, L);
        *(uint4*)(g_act_hi + off) = H;
        *(uint4*)(g_act_lo + off) = L;
        *(uint4*)(g_act_hi + ACT_ELEMS + off) = H;
        *(uint4*)(g_act_lo + ACT_ELEMS + off) = L;
    } else {
        uint4 z = make_uint4(0, 0, 0, 0);
        *(uint4*)(g_act_hi + off) = z;
        *(uint4*)(g_act_lo + off) = z;
    }
}

// ---------------------------------------------------------------- GEMM step (mma.sync)
// dst[b, IN+n] = relu( sum_k act[b,k] * mw[n,k] ), 3-term bf16 split, fp32 accum.
// 8 warps as 2(M) x 4(N); warp tile 64x48. 4-stage cp.async pipeline.
__global__ __launch_bounds__(256, 1)
void gemm_step(float* __restrict__ dout, int step) {
    extern __shared__ __align__(1024) char smem[];
    const uint32_t sb = s2u(smem);
    const int tid = threadIdx.x, warp = tid >> 5, lane = tid & 31;
    const int ntile = blockIdx.x, mtile = blockIdx.y;
    const int buf = step & 1;

    const __nv_bfloat16* srcAh = g_act_hi + (size_t)buf * ACT_ELEMS + (size_t)mtile * MT * L_DIM;
    const __nv_bfloat16* srcAl = g_act_lo + (size_t)buf * ACT_ELEMS + (size_t)mtile * MT * L_DIM;
    const __nv_bfloat16* srcBh = g_wt_hi + (size_t)ntile * NT * L_DIM;
    const __nv_bfloat16* srcBl = g_wt_lo + (size_t)ntile * NT * L_DIM;

    // ---- per-thread cp.async slot decode (10 granules of 16B per thread)
    // idx < 1024: A (hi:0-511, lo:512-1023), row=(idx>>2)&127, g=idx&3
    // else:       B (hi:0-767, lo:768-1535), row=kk>>2, g=kk&3
    uint32_t sOff[10];
    const __nv_bfloat16* gPtr[10];
    #pragma unroll
    for (int j = 0; j < 10; j++) {
        int idx = j * 256 + tid;
        if (idx < 1024) {
            int part = idx >> 9;
            int r = (idx >> 2) & 127, g4 = idx & 3;
            sOff[j] = part * STG_A + swz64((uint32_t)(r * ROWB + g4 * 16));
            gPtr[j] = (part ? srcAl : srcAh) + (size_t)r * L_DIM + g4 * 8;
        } else {
            int k = idx - 1024;
            int part = (k >= 768);
            int kk = part ? k - 768 : k;
            int r = kk >> 2, g4 = kk & 3;
            sOff[j] = 2 * STG_A + part * STG_B + swz64((uint32_t)(r * ROWB + g4 * 16));
            gPtr[j] = (part ? srcBl : srcBh) + (size_t)r * L_DIM + g4 * 8;
        }
    }

    // ---- ldmatrix lane offsets (within a stage's A / B part)
    const int m0 = (warp >> 2) * 64;     // warp M origin
    const int n0 = (warp & 3) * 48;      // warp N origin
    uint32_t aOff[4][2], bOff[3][2];
    #pragma unroll
    for (int mi = 0; mi < 4; mi++)
        #pragma unroll
        for (int ks = 0; ks < 2; ks++) {
            int row = m0 + mi * 16 + (lane & 15);
            int col = ks * 32 + (lane >> 4) * 16;
            aOff[mi][ks] = swz64((uint32_t)(row * ROWB + col));
        }
    #pragma unroll
    for (int nb = 0; nb < 3; nb++)
        #pragma unroll
        for (int ks = 0; ks < 2; ks++) {
            int grp = lane >> 3;
            int row = n0 + nb * 16 + ((grp & 2) << 2) + (lane & 7);
            int col = ks * 32 + (grp & 1) * 16;
            bOff[nb][ks] = swz64((uint32_t)(row * ROWB + col));
        }

    float acc[4][6][4];
    #pragma unroll
    for (int mi = 0; mi < 4; mi++)
        #pragma unroll
        for (int ni = 0; ni < 6; ni++)
            #pragma unroll
            for (int q = 0; q < 4; q++) acc[mi][ni][q] = 0.0f;

    // ---- prologue: stages 0..2 (chunks 0..2)
    #pragma unroll
    for (int c = 0; c < NSTAGES - 1; c++) {
        uint32_t stBase = sb + c * STAGE;
        #pragma unroll
        for (int j = 0; j < 10; j++) cp16(stBase + sOff[j], gPtr[j] + c * KC);
        cp_commit();
    }

    // ---- mainloop
    for (int i = 0; i < NKC; i++) {
        __syncthreads();                           // stage (i+3)&3 free to overwrite
        int cNext = i + NSTAGES - 1;
        if (cNext < NKC) {
            uint32_t stBase = sb + (cNext & (NSTAGES - 1)) * STAGE;
            #pragma unroll
            for (int j = 0; j < 10; j++) cp16(stBase + sOff[j], gPtr[j] + cNext * KC);
        }
        cp_commit();
        cp_wait<NSTAGES - 1>();
        __syncthreads();                           // publish stage i to all warps

        const uint32_t aHiB = sb + (i & (NSTAGES - 1)) * STAGE;
        const uint32_t aLoB = aHiB + STG_A;
        const uint32_t bHiB = aHiB + 2 * STG_A;
        const uint32_t bLoB = bHiB + STG_B;

        #pragma unroll
        for (int ks = 0; ks < 2; ks++) {
            uint32_t ah[4][4], al[4][4], bh[6][2], bl[6][2];
            #pragma unroll
            for (int mi = 0; mi < 4; mi++) {
                ldsm4(ah[mi], aHiB + aOff[mi][ks]);
                ldsm4(al[mi], aLoB + aOff[mi][ks]);
            }
            #pragma unroll
            for (int nb = 0; nb < 3; nb++) {
                uint32_t t[4];
                ldsm4(t, bHiB + bOff[nb][ks]);
                bh[2*nb][0] = t[0]; bh[2*nb][1] = t[1];
                bh[2*nb+1][0] = t[2]; bh[2*nb+1][1] = t[3];
                ldsm4(t, bLoB + bOff[nb][ks]);
                bl[2*nb][0] = t[0]; bl[2*nb][1] = t[1];
                bl[2*nb+1][0] = t[2]; bl[2*nb+1][1] = t[3];
            }
            #pragma unroll
            for (int mi = 0; mi < 4; mi++)
                #pragma unroll
                for (int ni = 0; ni < 6; ni++) {
                    mma16816(acc[mi][ni], ah[mi], bh[ni]);
                    mma16816(acc[mi][ni], ah[mi], bl[ni]);
                    mma16816(acc[mi][ni], al[mi], bh[ni]);
                }
        }
    }

    // ---- epilogue: relu, fp32 -> dout, bf16 hi/lo -> next act buffer
    __nv_bfloat16* dHi = g_act_hi + (size_t)(1 - buf) * ACT_ELEMS;
    __nv_bfloat16* dLo = g_act_lo + (size_t)(1 - buf) * ACT_ELEMS;
    #pragma unroll
    for (int mi = 0; mi < 4; mi++) {
        const int r0 = mtile * MT + m0 + mi * 16 + (lane >> 2);
        #pragma unroll
        for (int ni = 0; ni < 6; ni++) {
            const int col = ntile * NT + n0 + ni * 8 + (lane & 3) * 2;  // 0..3071
            #pragma unroll
            for (int h = 0; h < 2; h++) {
                const int row = r0 + h * 8;
                float v0 = fmaxf(acc[mi][ni][2*h],   0.0f);
                float v1 = fmaxf(acc[mi][ni][2*h+1], 0.0f);
                size_t off = (size_t)row * L_DIM + IN_DIM + col;
                *(float2*)(dout + off) = make_float2(v0, v1);
                uint32_t H, L;
                split2(v0, v1, H, L);
                *(uint32_t*)(dHi + off) = H;
                *(uint32_t*)(dLo + off) = L;
            }
        }
    }
}

// ---------------------------------------------------------------- hid row-normalize
// Normalize fp32 hid in dout; rewrite bf16 hi/lo hid cols of the next act buffer.
__global__ __launch_bounds__(256)
void norm_hid(float* __restrict__ dout, int step) {
    const int row = blockIdx.x, t = threadIdx.x;
    float* hid = dout + (size_t)row * L_DIM + IN_DIM + OUT_DIM;
    float4 v0 = *(float4*)(hid + t * 8);
    float4 v1 = *(float4*)(hid + t * 8 + 4);
    float ss = v0.x*v0.x + v0.y*v0.y + v0.z*v0.z + v0.w*v0.w
             + v1.x*v1.x + v1.y*v1.y + v1.z*v1.z + v1.w*v1.w;
    __shared__ float red[8];
    __shared__ float s_scale;
    #pragma unroll
    for (int off = 16; off > 0; off >>= 1) ss += __shfl_xor_sync(0xFFFFFFFFu, ss, off);
    if ((t & 31) == 0) red[t >> 5] = ss;
    __syncthreads();
    if (t == 0) {
        float tot = 0.0f;
        #pragma unroll
        for (int w = 0; w < 8; w++) tot += red[w];
        s_scale = 1.0f / fmaxf(sqrtf(tot), EPS_N);
    }
    __syncthreads();
    const float sc = s_scale;
    v0.x *= sc; v0.y *= sc; v0.z *= sc; v0.w *= sc;
    v1.x *= sc; v1.y *= sc; v1.z *= sc; v1.w *= sc;
    *(float4*)(hid + t * 8)     = v0;
    *(float4*)(hid + t * 8 + 4) = v1;

    const int nbuf = 1 - (step & 1);
    size_t off = (size_t)nbuf * ACT_ELEMS + (size_t)row * L_DIM + IN_DIM + OUT_DIM + t * 8;
    float f[8] = {v0.x, v0.y, v0.z, v0.w, v1.x, v1.y, v1.z, v1.w};
    uint4 H, L;
    split8(f, H, L);
    *(uint4*)(g_act_hi + off) = H;
    *(uint4*)(g_act_lo + off) = L;
}

// ---------------------------------------------------------------- launch
extern "C" void kernel_launch(void* const* d_in, const int* in_sizes, int n_in,
                              void* d_out, int out_size) {
    const float* x = (const float*)d_in[0];
    const float* W = (const float*)d_in[2];
    const float* A = (const float*)d_in[3];
    float* out = (float*)d_out;

    cudaFuncSetAttribute(gemm_step, cudaFuncAttributeMaxDynamicSharedMemorySize, SMEM_TOT);

    prep_w<<<dim3(L_DIM / 32, NCOLS / 32), dim3(32, 32)>>>(W, A);
    init_act<<<(B_DIM * 512) / 256, 256>>>(x, out);

    for (int s = 0; s < NSTEPS; s++) {
        gemm_step<<<dim3(NTILES, MTILES), 256, SMEM_TOT>>>(out, s);
        norm_hid<<<B_DIM, 256>>>(out, s);
    }
}

// round 6
// speedup vs baseline: 4.4817x; 1.0648x over previous
#include <cuda_runtime.h>
#include <cuda_bf16.h>
#include <stdint.h>
#include <math.h>

// ---------------------------------------------------------------- constants
#define IN_DIM   1024
#define OUT_DIM  1024
#define HID_DIM  2048
#define L_DIM    4096
#define B_DIM    1024
#define NCOLS    3072
#define NSTEPS   32
#define EPS_N    1e-12f

// GEMM: C(M=1024, N=3072, K=4096). CTA tile 128x192, K-chunk 32.
#define MT       128
#define NT       192
#define KC       32
#define NKC      128
#define MTILES   8
#define NTILES   16             // grid 16x8 = 128 CTAs (one wave, 1 CTA/SM)

#define ROWB     64             // bytes per smem row (32 bf16)
#define STG_A    (MT*ROWB)      // 8192
#define STG_B    (NT*ROWB)      // 12288
#define STAGE    (2*STG_A + 2*STG_B)   // 40960
#define NSTAGES  4
#define SMEM_TOT (NSTAGES*STAGE)       // 163840

#define ACT_ELEMS ((size_t)B_DIM * L_DIM)

// ---------------------------------------------------------------- device scratch
__device__ __align__(1024) __nv_bfloat16 g_wt_hi[(size_t)NCOLS * L_DIM];
__device__ __align__(1024) __nv_bfloat16 g_wt_lo[(size_t)NCOLS * L_DIM];
__device__ __align__(1024) __nv_bfloat16 g_act_hi[2 * ACT_ELEMS];
__device__ __align__(1024) __nv_bfloat16 g_act_lo[2 * ACT_ELEMS];

// ---------------------------------------------------------------- helpers
__device__ __forceinline__ uint32_t swz64(uint32_t b) { return b ^ ((b >> 3) & 0x30u); }

__device__ __forceinline__ uint32_t s2u(const void* p) {
    uint32_t a;
    asm("{ .reg .u64 t; cvta.to.shared.u64 t, %1; cvt.u32.u64 %0, t; }" : "=r"(a) : "l"(p));
    return a;
}
__device__ __forceinline__ void cp16(uint32_t dst, const void* src) {
    asm volatile("cp.async.cg.shared.global [%0], [%1], 16;" :: "r"(dst), "l"(src));
}
__device__ __forceinline__ void cp_commit() { asm volatile("cp.async.commit_group;"); }
template <int N>
__device__ __forceinline__ void cp_wait() { asm volatile("cp.async.wait_group %0;" :: "n"(N)); }

__device__ __forceinline__ void ldsm4(uint32_t* r, uint32_t addr) {
    asm volatile("ldmatrix.sync.aligned.m8n8.x4.shared.b16 {%0,%1,%2,%3}, [%4];"
                 : "=r"(r[0]), "=r"(r[1]), "=r"(r[2]), "=r"(r[3]) : "r"(addr));
}
__device__ __forceinline__ void mma16816(float* c, const uint32_t* a, const uint32_t* b) {
    asm volatile("mma.sync.aligned.m16n8k16.row.col.f32.bf16.bf16.f32 "
                 "{%0,%1,%2,%3}, {%4,%5,%6,%7}, {%8,%9}, {%0,%1,%2,%3};"
                 : "+f"(c[0]), "+f"(c[1]), "+f"(c[2]), "+f"(c[3])
                 : "r"(a[0]), "r"(a[1]), "r"(a[2]), "r"(a[3]), "r"(b[0]), "r"(b[1]));
}

__device__ __forceinline__ void split2(float f0, float f1, uint32_t& H, uint32_t& L) {
    __nv_bfloat16 h0 = __float2bfloat16_rn(f0);
    __nv_bfloat16 h1 = __float2bfloat16_rn(f1);
    __nv_bfloat16 l0 = __float2bfloat16_rn(f0 - __bfloat162float(h0));
    __nv_bfloat16 l1 = __float2bfloat16_rn(f1 - __bfloat162float(h1));
    H = (uint32_t)__bfloat16_as_ushort(h0) | ((uint32_t)__bfloat16_as_ushort(h1) << 16);
    L = (uint32_t)__bfloat16_as_ushort(l0) | ((uint32_t)__bfloat16_as_ushort(l1) << 16);
}
__device__ __forceinline__ void split8(const float* f, uint4& H, uint4& L) {
    uint32_t hw[4], lw[4];
    #pragma unroll
    for (int p = 0; p < 4; p++) split2(f[2*p], f[2*p+1], hw[p], lw[p]);
    H = make_uint4(hw[0], hw[1], hw[2], hw[3]);
    L = make_uint4(lw[0], lw[1], lw[2], lw[3]);
}
__device__ __forceinline__ float rc2(uint32_t w, int hi) {
    return __bfloat162float(__ushort_as_bfloat16((unsigned short)(hi ? (w >> 16) : (w & 0xFFFFu))));
}

// ---------------------------------------------------------------- prep weights
__global__ void prep_w(const float* __restrict__ W, const float* __restrict__ A) {
    __shared__ float tile[32][33];
    const int i0 = blockIdx.y * 32, j0 = blockIdx.x * 32;
    const int tx = threadIdx.x, ty = threadIdx.y;
    tile[ty][tx] = A[(size_t)(j0 + ty) * L_DIM + (IN_DIM + i0 + tx)];
    __syncthreads();
    const int i = i0 + ty, j = j0 + tx;
    float v = W[(size_t)(IN_DIM + i) * L_DIM + j] * tile[tx][ty];
    __nv_bfloat16 h = __float2bfloat16_rn(v);
    __nv_bfloat16 l = __float2bfloat16_rn(v - __bfloat162float(h));
    g_wt_hi[(size_t)i * L_DIM + j] = h;
    g_wt_lo[(size_t)i * L_DIM + j] = l;
}

// ---------------------------------------------------------------- init activations
__global__ void init_act(const float* __restrict__ x, float* __restrict__ dout) {
    int g = blockIdx.x * blockDim.x + threadIdx.x;
    int row = g >> 9;
    int k0 = (g & 511) * 8;
    size_t off = (size_t)row * L_DIM + k0;
    if (k0 < IN_DIM) {
        float4 a = *(const float4*)(x + (size_t)row * IN_DIM + k0);
        float4 b = *(const float4*)(x + (size_t)row * IN_DIM + k0 + 4);
        *(float4*)(dout + off)     = a;     // final-output x columns
        *(float4*)(dout + off + 4) = b;
        float f[8] = {a.x, a.y, a.z, a.w, b.x, b.y, b.z, b.w};
        uint4 H, L;
        split8(f, H, L);
        *(uint4*)(g_act_hi + off) = H;
        *(uint4*)(g_act_lo + off) = L;
        *(uint4*)(g_act_hi + ACT_ELEMS + off) = H;
        *(uint4*)(g_act_lo + ACT_ELEMS + off) = L;
    } else {
        uint4 z = make_uint4(0, 0, 0, 0);
        *(uint4*)(g_act_hi + off) = z;
        *(uint4*)(g_act_lo + off) = z;
    }
}

// ---------------------------------------------------------------- GEMM step
// 512 threads, warp grid 4(M) x 4(N), warp tile 32x48.
// 4-stage cp.async pipeline, ONE __syncthreads per chunk.
// steps<31: store bf16 hi/lo only; step 31: store fp32 only.
__global__ __launch_bounds__(512, 1)
void gemm_step(float* __restrict__ dout, int step) {
    extern __shared__ __align__(1024) char smem[];
    const uint32_t sb = s2u(smem);
    const int tid = threadIdx.x, warp = tid >> 5, lane = tid & 31;
    const int ntile = blockIdx.x, mtile = blockIdx.y;
    const int buf = step & 1;
    const bool last = (step == NSTEPS - 1);

    const __nv_bfloat16* srcAh = g_act_hi + (size_t)buf * ACT_ELEMS + (size_t)mtile * MT * L_DIM;
    const __nv_bfloat16* srcAl = g_act_lo + (size_t)buf * ACT_ELEMS + (size_t)mtile * MT * L_DIM;
    const __nv_bfloat16* srcBh = g_wt_hi + (size_t)ntile * NT * L_DIM;
    const __nv_bfloat16* srcBl = g_wt_lo + (size_t)ntile * NT * L_DIM;

    // ---- cp.async slots: 2560 granules of 16B, 5 per thread
    uint32_t sOff[5];
    const __nv_bfloat16* gPtr[5];
    #pragma unroll
    for (int j = 0; j < 5; j++) {
        int idx = j * 512 + tid;
        if (idx < 1024) {
            int part = idx >> 9;
            int r = (idx >> 2) & 127, g4 = idx & 3;
            sOff[j] = part * STG_A + swz64((uint32_t)(r * ROWB + g4 * 16));
            gPtr[j] = (part ? srcAl : srcAh) + (size_t)r * L_DIM + g4 * 8;
        } else {
            int k = idx - 1024;
            int part = (k >= 768);
            int kk = part ? k - 768 : k;
            int r = kk >> 2, g4 = kk & 3;
            sOff[j] = 2 * STG_A + part * STG_B + swz64((uint32_t)(r * ROWB + g4 * 16));
            gPtr[j] = (part ? srcBl : srcBh) + (size_t)r * L_DIM + g4 * 8;
        }
    }

    // ---- fragment smem offsets (same formulas as round-4, smaller warp tile)
    const int m0 = (warp >> 2) * 32;     // warp M origin (4 M-warps)
    const int n0 = (warp & 3) * 48;      // warp N origin (4 N-warps)
    uint32_t aOff[2][2], bOff[3][2];
    #pragma unroll
    for (int mi = 0; mi < 2; mi++)
        #pragma unroll
        for (int ks = 0; ks < 2; ks++) {
            int row = m0 + mi * 16 + (lane & 15);
            int col = ks * 32 + (lane >> 4) * 16;
            aOff[mi][ks] = swz64((uint32_t)(row * ROWB + col));
        }
    #pragma unroll
    for (int nb = 0; nb < 3; nb++)
        #pragma unroll
        for (int ks = 0; ks < 2; ks++) {
            int grp = lane >> 3;
            int row = n0 + nb * 16 + ((grp & 2) << 2) + (lane & 7);
            int col = ks * 32 + (grp & 1) * 16;
            bOff[nb][ks] = swz64((uint32_t)(row * ROWB + col));
        }

    float acc[2][6][4];
    #pragma unroll
    for (int mi = 0; mi < 2; mi++)
        #pragma unroll
        for (int ni = 0; ni < 6; ni++)
            #pragma unroll
            for (int q = 0; q < 4; q++) acc[mi][ni][q] = 0.0f;

    // ---- prologue: stages 0..2
    #pragma unroll
    for (int c = 0; c < NSTAGES - 1; c++) {
        uint32_t stBase = sb + c * STAGE;
        #pragma unroll
        for (int j = 0; j < 5; j++) cp16(stBase + sOff[j], gPtr[j] + c * KC);
        cp_commit();
    }

    // ---- mainloop: one sync per chunk
    for (int i = 0; i < NKC; i++) {
        cp_wait<NSTAGES - 2>();                    // stage i arrived (this thread)
        __syncthreads();                           // publish; stage i-1 now free
        int cNext = i + NSTAGES - 1;
        if (cNext < NKC) {
            uint32_t stBase = sb + (cNext & (NSTAGES - 1)) * STAGE;
            #pragma unroll
            for (int j = 0; j < 5; j++) cp16(stBase + sOff[j], gPtr[j] + cNext * KC);
        }
        cp_commit();

        const uint32_t aHiB = sb + (i & (NSTAGES - 1)) * STAGE;
        const uint32_t aLoB = aHiB + STG_A;
        const uint32_t bHiB = aHiB + 2 * STG_A;
        const uint32_t bLoB = bHiB + STG_B;

        #pragma unroll
        for (int ks = 0; ks < 2; ks++) {
            uint32_t ah[2][4], al[2][4], bh[6][2], bl[6][2];
            #pragma unroll
            for (int mi = 0; mi < 2; mi++) {
                ldsm4(ah[mi], aHiB + aOff[mi][ks]);
                ldsm4(al[mi], aLoB + aOff[mi][ks]);
            }
            #pragma unroll
            for (int nb = 0; nb < 3; nb++) {
                uint32_t t[4];
                ldsm4(t, bHiB + bOff[nb][ks]);
                bh[2*nb][0] = t[0]; bh[2*nb][1] = t[1];
                bh[2*nb+1][0] = t[2]; bh[2*nb+1][1] = t[3];
                ldsm4(t, bLoB + bOff[nb][ks]);
                bl[2*nb][0] = t[0]; bl[2*nb][1] = t[1];
                bl[2*nb+1][0] = t[2]; bl[2*nb+1][1] = t[3];
            }
            #pragma unroll
            for (int mi = 0; mi < 2; mi++)
                #pragma unroll
                for (int ni = 0; ni < 6; ni++) {
                    mma16816(acc[mi][ni], ah[mi], bh[ni]);
                    mma16816(acc[mi][ni], ah[mi], bl[ni]);
                    mma16816(acc[mi][ni], al[mi], bh[ni]);
                }
        }
    }

    // ---- epilogue
    __nv_bfloat16* dHi = g_act_hi + (size_t)(1 - buf) * ACT_ELEMS;
    __nv_bfloat16* dLo = g_act_lo + (size_t)(1 - buf) * ACT_ELEMS;
    #pragma unroll
    for (int mi = 0; mi < 2; mi++) {
        const int r0 = mtile * MT + m0 + mi * 16 + (lane >> 2);
        #pragma unroll
        for (int ni = 0; ni < 6; ni++) {
            const int col = ntile * NT + n0 + ni * 8 + (lane & 3) * 2;
            #pragma unroll
            for (int h = 0; h < 2; h++) {
                const int row = r0 + h * 8;
                float v0 = fmaxf(acc[mi][ni][2*h],   0.0f);
                float v1 = fmaxf(acc[mi][ni][2*h+1], 0.0f);
                size_t off = (size_t)row * L_DIM + IN_DIM + col;
                if (last) {
                    *(float2*)(dout + off) = make_float2(v0, v1);
                } else {
                    uint32_t H, L;
                    split2(v0, v1, H, L);
                    *(uint32_t*)(dHi + off) = H;
                    *(uint32_t*)(dLo + off) = L;
                }
            }
        }
    }
}

// ---------------------------------------------------------------- hid row-normalize
// steps<31: operate on bf16 hi/lo of next act buffer (reconstruct fp32 = hi+lo).
// step 31: operate on fp32 hid in dout.
__global__ __launch_bounds__(256)
void norm_hid(float* __restrict__ dout, int step) {
    const int row = blockIdx.x, t = threadIdx.x;
    const bool last = (step == NSTEPS - 1);
    float f[8];
    size_t aOff = 0;
    if (last) {
        float4 v0 = *(float4*)(dout + (size_t)row * L_DIM + IN_DIM + OUT_DIM + t * 8);
        float4 v1 = *(float4*)(dout + (size_t)row * L_DIM + IN_DIM + OUT_DIM + t * 8 + 4);
        f[0]=v0.x; f[1]=v0.y; f[2]=v0.z; f[3]=v0.w;
        f[4]=v1.x; f[5]=v1.y; f[6]=v1.z; f[7]=v1.w;
    } else {
        const int nbuf = 1 - (step & 1);
        aOff = (size_t)nbuf * ACT_ELEMS + (size_t)row * L_DIM + IN_DIM + OUT_DIM + t * 8;
        uint4 H = *(uint4*)(g_act_hi + aOff);
        uint4 L = *(uint4*)(g_act_lo + aOff);
        const uint32_t* hw = &H.x;
        const uint32_t* lw = &L.x;
        #pragma unroll
        for (int p = 0; p < 4; p++) {
            f[2*p]   = rc2(hw[p], 0) + rc2(lw[p], 0);
            f[2*p+1] = rc2(hw[p], 1) + rc2(lw[p], 1);
        }
    }
    float ss = 0.0f;
    #pragma unroll
    for (int q = 0; q < 8; q++) ss += f[q] * f[q];

    __shared__ float red[8];
    __shared__ float s_scale;
    #pragma unroll
    for (int off = 16; off > 0; off >>= 1) ss += __shfl_xor_sync(0xFFFFFFFFu, ss, off);
    if ((t & 31) == 0) red[t >> 5] = ss;
    __syncthreads();
    if (t == 0) {
        float tot = 0.0f;
        #pragma unroll
        for (int w = 0; w < 8; w++) tot += red[w];
        s_scale = 1.0f / fmaxf(sqrtf(tot), EPS_N);
    }
    __syncthreads();
    const float sc = s_scale;
    #pragma unroll
    for (int q = 0; q < 8; q++) f[q] *= sc;

    if (last) {
        *(float4*)(dout + (size_t)row * L_DIM + IN_DIM + OUT_DIM + t * 8)
            = make_float4(f[0], f[1], f[2], f[3]);
        *(float4*)(dout + (size_t)row * L_DIM + IN_DIM + OUT_DIM + t * 8 + 4)
            = make_float4(f[4], f[5], f[6], f[7]);
    } else {
        uint4 H, L;
        split8(f, H, L);
        *(uint4*)(g_act_hi + aOff) = H;
        *(uint4*)(g_act_lo + aOff) = L;
    }
}

// ---------------------------------------------------------------- launch
extern "C" void kernel_launch(void* const* d_in, const int* in_sizes, int n_in,
                              void* d_out, int out_size) {
    const float* x = (const float*)d_in[0];
    const float* W = (const float*)d_in[2];
    const float* A = (const float*)d_in[3];
    float* out = (float*)d_out;

    cudaFuncSetAttribute(gemm_step, cudaFuncAttributeMaxDynamicSharedMemorySize, SMEM_TOT);

    prep_w<<<dim3(L_DIM / 32, NCOLS / 32), dim3(32, 32)>>>(W, A);
    init_act<<<(B_DIM * 512) / 256, 256>>>(x, out);

    for (int s = 0; s < NSTEPS; s++) {
        gemm_step<<<dim3(NTILES, MTILES), 512, SMEM_TOT>>>(out, s);
        norm_hid<<<B_DIM, 256>>>(out, s);
    }
}

// round 8
// speedup vs baseline: 4.9782x; 1.1108x over previous
#include <cuda_runtime.h>
#include <cuda_bf16.h>
#include <stdint.h>
#include <math.h>

// ---------------------------------------------------------------- constants
#define IN_DIM   1024
#define OUT_DIM  1024
#define L_DIM    4096
#define B_DIM    1024
#define NCOLS    3072
#define NSTEPS   32
#define EPS_N    1e-12f

// GEMM: C(M=1024, N=3072, K=4096). CTA 128x192, K-chunk 32.
#define MT       128
#define NT       192
#define KC       32
#define NKC      128
#define MTILES   8
#define NTILES   16            // grid 16x8 = 128 CTAs

#define ROWB     64            // bytes per row (32 bf16)
#define ABLK     (MT*ROWB)     // 8192  (one A hi or lo chunk block)
#define BBLK     (NT*ROWB)     // 12288 (one B hi or lo chunk block)
#define STAGE    (2*ABLK + 2*BBLK)   // 40960
#define NSTG     4
#define SMEM_DATA (NSTG*STAGE)       // 163840
#define SMEM_TOT  (SMEM_DATA + 64)

#define ACT_BUF  ((size_t)MTILES * NKC * ABLK)   // 8 MB (bytes) per buffer
#define WT_TOT   ((size_t)NTILES * NKC * BBLK)   // 24 MB (bytes)

// ---------------------------------------------------------------- device scratch
// chunk-contiguous, swz64-pre-swizzled blocks
__device__ __align__(1024) char g_wt_hi[WT_TOT];
__device__ __align__(1024) char g_wt_lo[WT_TOT];
__device__ __align__(1024) char g_act_hi[2 * ACT_BUF];
__device__ __align__(1024) char g_act_lo[2 * ACT_BUF];

// ---------------------------------------------------------------- helpers
__device__ __forceinline__ uint32_t swz64(uint32_t b) { return b ^ ((b >> 3) & 0x30u); }

__device__ __forceinline__ uint32_t s2u(const void* p) {
    uint32_t a;
    asm("{ .reg .u64 t; cvta.to.shared.u64 t, %1; cvt.u32.u64 %0, t; }" : "=r"(a) : "l"(p));
    return a;
}
__device__ __forceinline__ void mbar_init(uint32_t a, uint32_t c) {
    asm volatile("mbarrier.init.shared.b64 [%0], %1;" :: "r"(a), "r"(c) : "memory");
}
__device__ __forceinline__ void mbar_expect_tx(uint32_t a, uint32_t bytes) {
    asm volatile("mbarrier.arrive.expect_tx.shared.b64 _, [%0], %1;" :: "r"(a), "r"(bytes) : "memory");
}
__device__ __forceinline__ void mbar_wait(uint32_t a, uint32_t par) {
    asm volatile("{\n\t.reg .pred P;\n\tWL_%=:\n\t"
                 "mbarrier.try_wait.parity.acquire.cta.shared::cta.b64 P, [%0], %1, 0x989680;\n\t"
                 "@P bra.uni WD_%=;\n\tbra.uni WL_%=;\n\tWD_%=:\n\t}"
                 :: "r"(a), "r"(par) : "memory");
}
__device__ __forceinline__ void bulk_g2s(uint32_t dst, const void* src, uint32_t bytes, uint32_t mbar) {
    asm volatile("cp.async.bulk.shared::cluster.global.mbarrier::complete_tx::bytes [%0], [%1], %2, [%3];"
                 :: "r"(dst), "l"(src), "r"(bytes), "r"(mbar) : "memory");
}
__device__ __forceinline__ void ldsm4(uint32_t* r, uint32_t addr) {
    asm volatile("ldmatrix.sync.aligned.m8n8.x4.shared.b16 {%0,%1,%2,%3}, [%4];"
                 : "=r"(r[0]), "=r"(r[1]), "=r"(r[2]), "=r"(r[3]) : "r"(addr));
}
__device__ __forceinline__ void mma16816(float* c, const uint32_t* a, const uint32_t* b) {
    asm volatile("mma.sync.aligned.m16n8k16.row.col.f32.bf16.bf16.f32 "
                 "{%0,%1,%2,%3}, {%4,%5,%6,%7}, {%8,%9}, {%0,%1,%2,%3};"
                 : "+f"(c[0]), "+f"(c[1]), "+f"(c[2]), "+f"(c[3])
                 : "r"(a[0]), "r"(a[1]), "r"(a[2]), "r"(a[3]), "r"(b[0]), "r"(b[1]));
}

__device__ __forceinline__ void split2(float f0, float f1, uint32_t& H, uint32_t& L) {
    __nv_bfloat16 h0 = __float2bfloat16_rn(f0);
    __nv_bfloat16 h1 = __float2bfloat16_rn(f1);
    __nv_bfloat16 l0 = __float2bfloat16_rn(f0 - __bfloat162float(h0));
    __nv_bfloat16 l1 = __float2bfloat16_rn(f1 - __bfloat162float(h1));
    H = (uint32_t)__bfloat16_as_ushort(h0) | ((uint32_t)__bfloat16_as_ushort(h1) << 16);
    L = (uint32_t)__bfloat16_as_ushort(l0) | ((uint32_t)__bfloat16_as_ushort(l1) << 16);
}
__device__ __forceinline__ void split8(const float* f, uint4& H, uint4& L) {
    uint32_t hw[4], lw[4];
    #pragma unroll
    for (int p = 0; p < 4; p++) split2(f[2*p], f[2*p+1], hw[p], lw[p]);
    H = make_uint4(hw[0], hw[1], hw[2], hw[3]);
    L = make_uint4(lw[0], lw[1], lw[2], lw[3]);
}
__device__ __forceinline__ float rc2(uint32_t w, int hi) {
    return __bfloat162float(__ushort_as_bfloat16((unsigned short)(hi ? (w >> 16) : (w & 0xFFFFu))));
}

// act tiled address: buf, global row (0..1023), act k-index (0..4095)
__device__ __forceinline__ size_t act_off(int row, int k) {
    int mtile = row >> 7, rin = row & 127;
    int chunk = k >> 5,  cc = k & 31;
    return (size_t)(mtile * NKC + chunk) * ABLK + swz64((uint32_t)(rin * ROWB + cc * 2));
}

// ---------------------------------------------------------------- prep weights
// mw[i][j] = W[IN+i][j] * A[j][IN+i]; bf16 hi/lo; tiled+swizzled blocks.
__global__ void prep_w(const float* __restrict__ W, const float* __restrict__ A) {
    __shared__ float tile[32][33];
    const int i0 = blockIdx.y * 32, j0 = blockIdx.x * 32;
    const int tx = threadIdx.x, ty = threadIdx.y;
    tile[ty][tx] = A[(size_t)(j0 + ty) * L_DIM + (IN_DIM + i0 + tx)];
    __syncthreads();
    const int i = i0 + ty, j = j0 + tx;
    float v = W[(size_t)(IN_DIM + i) * L_DIM + j] * tile[tx][ty];
    __nv_bfloat16 h = __float2bfloat16_rn(v);
    __nv_bfloat16 l = __float2bfloat16_rn(v - __bfloat162float(h));
    const int ntile = i / NT, r = i % NT;
    const int chunk = j >> 5, cc = j & 31;
    size_t off = (size_t)(ntile * NKC + chunk) * BBLK + swz64((uint32_t)(r * ROWB + cc * 2));
    *(__nv_bfloat16*)(g_wt_hi + off) = h;
    *(__nv_bfloat16*)(g_wt_lo + off) = l;
}

// ---------------------------------------------------------------- init activations
// dout x-cols = x (fp32, survive to final output). act buffers (tiled bf16):
// x chunks (k<1024) -> both buffers; chunks k>=1024 of buffer 0 -> zero.
__global__ void init_act(const float* __restrict__ x, float* __restrict__ dout) {
    int g = blockIdx.x * blockDim.x + threadIdx.x;   // 1024 rows * 512 groups
    int row = g >> 9;
    int k0 = (g & 511) * 8;
    size_t off = act_off(row, k0);
    if (k0 < IN_DIM) {
        float4 a = *(const float4*)(x + (size_t)row * IN_DIM + k0);
        float4 b = *(const float4*)(x + (size_t)row * IN_DIM + k0 + 4);
        *(float4*)(dout + (size_t)row * L_DIM + k0)     = a;
        *(float4*)(dout + (size_t)row * L_DIM + k0 + 4) = b;
        float f[8] = {a.x, a.y, a.z, a.w, b.x, b.y, b.z, b.w};
        uint4 H, L;
        split8(f, H, L);
        *(uint4*)(g_act_hi + off) = H;
        *(uint4*)(g_act_lo + off) = L;
        *(uint4*)(g_act_hi + ACT_BUF + off) = H;
        *(uint4*)(g_act_lo + ACT_BUF + off) = L;
    } else {
        uint4 z = make_uint4(0, 0, 0, 0);
        *(uint4*)(g_act_hi + off) = z;
        *(uint4*)(g_act_lo + off) = z;
    }
}

// ---------------------------------------------------------------- GEMM step
// 256 threads, warp grid 2(M)x4(N), warp tile 64x48.
// Operand feed: 4 cp.async.bulk per chunk (elected thread), 4-stage mbarrier pipe.
__global__ __launch_bounds__(256, 1)
void gemm_step(float* __restrict__ dout, int step) {
    extern __shared__ __align__(1024) char smem[];
    const uint32_t sb = s2u(smem);
    const int tid = threadIdx.x, warp = tid >> 5, lane = tid & 31;
    const int ntile = blockIdx.x, mtile = blockIdx.y;
    const int buf = step & 1;
    const bool last = (step == NSTEPS - 1);

    const char* srcAh = g_act_hi + (size_t)buf * ACT_BUF + (size_t)mtile * NKC * ABLK;
    const char* srcAl = g_act_lo + (size_t)buf * ACT_BUF + (size_t)mtile * NKC * ABLK;
    const char* srcBh = g_wt_hi + (size_t)ntile * NKC * BBLK;
    const char* srcBl = g_wt_lo + (size_t)ntile * NKC * BBLK;

    const uint32_t mb = sb + SMEM_DATA;            // 4 mbarriers, 8B apart
    if (tid == 0) {
        #pragma unroll
        for (int s = 0; s < NSTG; s++) mbar_init(mb + 8 * s, 1);
    }
    __syncthreads();

    // prologue: chunks 0..2
    if (tid == 0) {
        #pragma unroll
        for (int c = 0; c < NSTG - 1; c++) {
            uint32_t st = sb + c * STAGE;
            mbar_expect_tx(mb + 8 * c, STAGE);
            bulk_g2s(st,                   srcAh + (size_t)c * ABLK, ABLK, mb + 8 * c);
            bulk_g2s(st + ABLK,            srcAl + (size_t)c * ABLK, ABLK, mb + 8 * c);
            bulk_g2s(st + 2 * ABLK,        srcBh + (size_t)c * BBLK, BBLK, mb + 8 * c);
            bulk_g2s(st + 2 * ABLK + BBLK, srcBl + (size_t)c * BBLK, BBLK, mb + 8 * c);
        }
    }

    // fragment smem offsets (proven round-4 formulas)
    const int m0 = (warp >> 2) * 64;     // 2 M-warps
    const int n0 = (warp & 3) * 48;      // 4 N-warps
    uint32_t aOff[4][2], bOff[3][2];
    #pragma unroll
    for (int mi = 0; mi < 4; mi++)
        #pragma unroll
        for (int ks = 0; ks < 2; ks++) {
            int row = m0 + mi * 16 + (lane & 15);
            int col = ks * 32 + (lane >> 4) * 16;
            aOff[mi][ks] = swz64((uint32_t)(row * ROWB + col));
        }
    #pragma unroll
    for (int nb = 0; nb < 3; nb++)
        #pragma unroll
        for (int ks = 0; ks < 2; ks++) {
            int grp = lane >> 3;
            int row = n0 + nb * 16 + ((grp & 2) << 2) + (lane & 7);
            int col = ks * 32 + (grp & 1) * 16;
            bOff[nb][ks] = swz64((uint32_t)(row * ROWB + col));
        }

    float acc[4][6][4];
    #pragma unroll
    for (int mi = 0; mi < 4; mi++)
        #pragma unroll
        for (int ni = 0; ni < 6; ni++)
            #pragma unroll
            for (int q = 0; q < 4; q++) acc[mi][ni][q] = 0.0f;

    // mainloop
    for (int i = 0; i < NKC; i++) {
        const int st = i & (NSTG - 1);
        mbar_wait(mb + 8 * st, (uint32_t)((i >> 2) & 1));

        const uint32_t aHiB = sb + st * STAGE;
        const uint32_t aLoB = aHiB + ABLK;
        const uint32_t bHiB = aHiB + 2 * ABLK;
        const uint32_t bLoB = bHiB + BBLK;

        #pragma unroll
        for (int ks = 0; ks < 2; ks++) {
            uint32_t ah[4][4], al[4][4], bh[6][2], bl[6][2];
            #pragma unroll
            for (int mi = 0; mi < 4; mi++) {
                ldsm4(ah[mi], aHiB + aOff[mi][ks]);
                ldsm4(al[mi], aLoB + aOff[mi][ks]);
            }
            #pragma unroll
            for (int nb = 0; nb < 3; nb++) {
                uint32_t t[4];
                ldsm4(t, bHiB + bOff[nb][ks]);
                bh[2*nb][0] = t[0]; bh[2*nb][1] = t[1];
                bh[2*nb+1][0] = t[2]; bh[2*nb+1][1] = t[3];
                ldsm4(t, bLoB + bOff[nb][ks]);
                bl[2*nb][0] = t[0]; bl[2*nb][1] = t[1];
                bl[2*nb+1][0] = t[2]; bl[2*nb+1][1] = t[3];
            }
            #pragma unroll
            for (int mi = 0; mi < 4; mi++)
                #pragma unroll
                for (int ni = 0; ni < 6; ni++) {
                    mma16816(acc[mi][ni], ah[mi], bh[ni]);
                    mma16816(acc[mi][ni], ah[mi], bl[ni]);
                    mma16816(acc[mi][ni], al[mi], bh[ni]);
                }
        }

        __syncthreads();     // all warps consumed stage of chunk i-1 and i
        const int cN = i + NSTG - 1;
        if (tid == 0 && cN < NKC) {
            const int sN = cN & (NSTG - 1);
            uint32_t stB = sb + sN * STAGE;
            mbar_expect_tx(mb + 8 * sN, STAGE);
            bulk_g2s(stB,                   srcAh + (size_t)cN * ABLK, ABLK, mb + 8 * sN);
            bulk_g2s(stB + ABLK,            srcAl + (size_t)cN * ABLK, ABLK, mb + 8 * sN);
            bulk_g2s(stB + 2 * ABLK,        srcBh + (size_t)cN * BBLK, BBLK, mb + 8 * sN);
            bulk_g2s(stB + 2 * ABLK + BBLK, srcBl + (size_t)cN * BBLK, BBLK, mb + 8 * sN);
        }
    }

    // epilogue
    char* dHi = g_act_hi + (size_t)(1 - buf) * ACT_BUF;
    char* dLo = g_act_lo + (size_t)(1 - buf) * ACT_BUF;
    #pragma unroll
    for (int mi = 0; mi < 4; mi++) {
        const int r0 = mtile * MT + m0 + mi * 16 + (lane >> 2);
        #pragma unroll
        for (int ni = 0; ni < 6; ni++) {
            const int n = ntile * NT + n0 + ni * 8 + (lane & 3) * 2;   // 0..3071
            #pragma unroll
            for (int h = 0; h < 2; h++) {
                const int row = r0 + h * 8;
                float v0 = fmaxf(acc[mi][ni][2*h],   0.0f);
                float v1 = fmaxf(acc[mi][ni][2*h+1], 0.0f);
                if (last) {
                    *(float2*)(dout + (size_t)row * L_DIM + IN_DIM + n) = make_float2(v0, v1);
                } else {
                    uint32_t H, L;
                    split2(v0, v1, H, L);
                    size_t off = act_off(row, IN_DIM + n);
                    *(uint32_t*)(dHi + off) = H;
                    *(uint32_t*)(dLo + off) = L;
                }
            }
        }
    }
}

// ---------------------------------------------------------------- hid row-normalize
__global__ __launch_bounds__(256)
void norm_hid(float* __restrict__ dout, int step) {
    const int row = blockIdx.x, t = threadIdx.x;
    const bool last = (step == NSTEPS - 1);
    float f[8];
    size_t aOff = 0;
    if (last) {
        float4 v0 = *(float4*)(dout + (size_t)row * L_DIM + IN_DIM + OUT_DIM + t * 8);
        float4 v1 = *(float4*)(dout + (size_t)row * L_DIM + IN_DIM + OUT_DIM + t * 8 + 4);
        f[0]=v0.x; f[1]=v0.y; f[2]=v0.z; f[3]=v0.w;
        f[4]=v1.x; f[5]=v1.y; f[6]=v1.z; f[7]=v1.w;
    } else {
        const int nbuf = 1 - (step & 1);
        aOff = (size_t)nbuf * ACT_BUF + act_off(row, IN_DIM + OUT_DIM + t * 8);
        uint4 H = *(uint4*)(g_act_hi + aOff);
        uint4 L = *(uint4*)(g_act_lo + aOff);
        const uint32_t* hw = &H.x;
        const uint32_t* lw = &L.x;
        #pragma unroll
        for (int p = 0; p < 4; p++) {
            f[2*p]   = rc2(hw[p], 0) + rc2(lw[p], 0);
            f[2*p+1] = rc2(hw[p], 1) + rc2(lw[p], 1);
        }
    }
    float ss = 0.0f;
    #pragma unroll
    for (int q = 0; q < 8; q++) ss += f[q] * f[q];

    __shared__ float red[8];
    __shared__ float s_scale;
    #pragma unroll
    for (int off = 16; off > 0; off >>= 1) ss += __shfl_xor_sync(0xFFFFFFFFu, ss, off);
    if ((t & 31) == 0) red[t >> 5] = ss;
    __syncthreads();
    if (t == 0) {
        float tot = 0.0f;
        #pragma unroll
        for (int w = 0; w < 8; w++) tot += red[w];
        s_scale = 1.0f / fmaxf(sqrtf(tot), EPS_N);
    }
    __syncthreads();
    const float sc = s_scale;
    #pragma unroll
    for (int q = 0; q < 8; q++) f[q] *= sc;

    if (last) {
        *(float4*)(dout + (size_t)row * L_DIM + IN_DIM + OUT_DIM + t * 8)
            = make_float4(f[0], f[1], f[2], f[3]);
        *(float4*)(dout + (size_t)row * L_DIM + IN_DIM + OUT_DIM + t * 8 + 4)
            = make_float4(f[4], f[5], f[6], f[7]);
    } else {
        uint4 H, L;
        split8(f, H, L);
        *(uint4*)(g_act_hi + aOff) = H;
        *(uint4*)(g_act_lo + aOff) = L;
    }
}

// ---------------------------------------------------------------- launch
extern "C" void kernel_launch(void* const* d_in, const int* in_sizes, int n_in,
                              void* d_out, int out_size) {
    const float* x = (const float*)d_in[0];
    const float* W = (const float*)d_in[2];
    const float* A = (const float*)d_in[3];
    float* out = (float*)d_out;

    cudaFuncSetAttribute(gemm_step, cudaFuncAttributeMaxDynamicSharedMemorySize, SMEM_TOT);

    prep_w<<<dim3(L_DIM / 32, NCOLS / 32), dim3(32, 32)>>>(W, A);
    init_act<<<(B_DIM * 512) / 256, 256>>>(x, out);

    for (int s = 0; s < NSTEPS; s++) {
        gemm_step<<<dim3(NTILES, MTILES), 256, SMEM_TOT>>>(out, s);
        norm_hid<<<B_DIM, 256>>>(out, s);
    }
}

// round 9
// speedup vs baseline: 5.2053x; 1.0456x over previous
#include <cuda_runtime.h>
#include <cuda_bf16.h>
#include <stdint.h>
#include <math.h>

// ---------------------------------------------------------------- constants
#define IN_DIM   1024
#define OUT_DIM  1024
#define L_DIM    4096
#define B_DIM    1024
#define NCOLS    3072
#define NSTEPS   32
#define EPS_N    1e-12f

// GEMM: C(M=1024, N=3072, K=4096). CTA 128x192, K-chunk 64.
#define MT       128
#define NT       192
#define KC       64
#define NKC      64
#define MTILES   8
#define NTILES   16            // grid 16x8 = 128 CTAs (one wave)

#define ROWB     128           // bytes per row (64 bf16) - SW128 atom
#define ABLK     (MT*ROWB)     // 16384
#define BBLK     (NT*ROWB)     // 24576
#define STAGE    (2*ABLK + 2*BBLK)   // 81920
#define NSTG     2
#define SMEM_DATA (NSTG*STAGE)       // 163840
#define SMEM_TOT  (SMEM_DATA + 64)

#define ACT_BUF  ((size_t)MTILES * NKC * ABLK)   // 8 MB per buffer
#define WT_TOT   ((size_t)NTILES * NKC * BBLK)   // 24 MB

// ---------------------------------------------------------------- device scratch
__device__ __align__(1024) char g_wt_hi[WT_TOT];
__device__ __align__(1024) char g_wt_lo[WT_TOT];
__device__ __align__(1024) char g_act_hi[2 * ACT_BUF];
__device__ __align__(1024) char g_act_lo[2 * ACT_BUF];
__device__ float g_scale[B_DIM];

// ---------------------------------------------------------------- helpers
__device__ __forceinline__ uint32_t swz128(uint32_t b) { return b ^ ((b >> 3) & 0x70u); }

__device__ __forceinline__ uint32_t s2u(const void* p) {
    uint32_t a;
    asm("{ .reg .u64 t; cvta.to.shared.u64 t, %1; cvt.u32.u64 %0, t; }" : "=r"(a) : "l"(p));
    return a;
}
__device__ __forceinline__ void mbar_init(uint32_t a, uint32_t c) {
    asm volatile("mbarrier.init.shared.b64 [%0], %1;" :: "r"(a), "r"(c) : "memory");
}
__device__ __forceinline__ void mbar_expect_tx(uint32_t a, uint32_t bytes) {
    asm volatile("mbarrier.arrive.expect_tx.shared.b64 _, [%0], %1;" :: "r"(a), "r"(bytes) : "memory");
}
__device__ __forceinline__ void mbar_wait(uint32_t a, uint32_t par) {
    asm volatile("{\n\t.reg .pred P;\n\tWL_%=:\n\t"
                 "mbarrier.try_wait.parity.acquire.cta.shared::cta.b64 P, [%0], %1, 0x989680;\n\t"
                 "@P bra.uni WD_%=;\n\tbra.uni WL_%=;\n\tWD_%=:\n\t}"
                 :: "r"(a), "r"(par) : "memory");
}
__device__ __forceinline__ void bulk_g2s(uint32_t dst, const void* src, uint32_t bytes, uint32_t mbar) {
    asm volatile("cp.async.bulk.shared::cluster.global.mbarrier::complete_tx::bytes [%0], [%1], %2, [%3];"
                 :: "r"(dst), "l"(src), "r"(bytes), "r"(mbar) : "memory");
}
__device__ __forceinline__ void ldsm4(uint32_t* r, uint32_t addr) {
    asm volatile("ldmatrix.sync.aligned.m8n8.x4.shared.b16 {%0,%1,%2,%3}, [%4];"
                 : "=r"(r[0]), "=r"(r[1]), "=r"(r[2]), "=r"(r[3]) : "r"(addr));
}
__device__ __forceinline__ void mma16816(float* c, const uint32_t* a, const uint32_t* b) {
    asm volatile("mma.sync.aligned.m16n8k16.row.col.f32.bf16.bf16.f32 "
                 "{%0,%1,%2,%3}, {%4,%5,%6,%7}, {%8,%9}, {%0,%1,%2,%3};"
                 : "+f"(c[0]), "+f"(c[1]), "+f"(c[2]), "+f"(c[3])
                 : "r"(a[0]), "r"(a[1]), "r"(a[2]), "r"(a[3]), "r"(b[0]), "r"(b[1]));
}

__device__ __forceinline__ void split2(float f0, float f1, uint32_t& H, uint32_t& L) {
    __nv_bfloat16 h0 = __float2bfloat16_rn(f0);
    __nv_bfloat16 h1 = __float2bfloat16_rn(f1);
    __nv_bfloat16 l0 = __float2bfloat16_rn(f0 - __bfloat162float(h0));
    __nv_bfloat16 l1 = __float2bfloat16_rn(f1 - __bfloat162float(h1));
    H = (uint32_t)__bfloat16_as_ushort(h0) | ((uint32_t)__bfloat16_as_ushort(h1) << 16);
    L = (uint32_t)__bfloat16_as_ushort(l0) | ((uint32_t)__bfloat16_as_ushort(l1) << 16);
}
__device__ __forceinline__ void split8(const float* f, uint4& H, uint4& L) {
    uint32_t hw[4], lw[4];
    #pragma unroll
    for (int p = 0; p < 4; p++) split2(f[2*p], f[2*p+1], hw[p], lw[p]);
    H = make_uint4(hw[0], hw[1], hw[2], hw[3]);
    L = make_uint4(lw[0], lw[1], lw[2], lw[3]);
}
__device__ __forceinline__ float rc2(uint32_t w, int hi) {
    return __bfloat162float(__ushort_as_bfloat16((unsigned short)(hi ? (w >> 16) : (w & 0xFFFFu))));
}

// act tiled address: global row (0..1023), act k-index (0..4095)
__device__ __forceinline__ size_t act_off(int row, int k) {
    int mtile = row >> 7, rin = row & 127;
    int chunk = k >> 6,  cc = k & 63;
    return (size_t)(mtile * NKC + chunk) * ABLK + swz128((uint32_t)(rin * ROWB + cc * 2));
}

// ---------------------------------------------------------------- prep weights
// mw[i][j] = W[IN+i][j] * A[j][IN+i]; bf16 hi/lo; KC=64 tiled + SW128 blocks.
__global__ void prep_w(const float* __restrict__ W, const float* __restrict__ A) {
    __shared__ float tile[32][33];
    const int i0 = blockIdx.y * 32, j0 = blockIdx.x * 32;
    const int tx = threadIdx.x, ty = threadIdx.y;
    tile[ty][tx] = A[(size_t)(j0 + ty) * L_DIM + (IN_DIM + i0 + tx)];
    __syncthreads();
    const int i = i0 + ty, j = j0 + tx;
    float v = W[(size_t)(IN_DIM + i) * L_DIM + j] * tile[tx][ty];
    __nv_bfloat16 h = __float2bfloat16_rn(v);
    __nv_bfloat16 l = __float2bfloat16_rn(v - __bfloat162float(h));
    const int ntile = i / NT, r = i % NT;
    const int chunk = j >> 6, cc = j & 63;
    size_t off = (size_t)(ntile * NKC + chunk) * BBLK + swz128((uint32_t)(r * ROWB + cc * 2));
    *(__nv_bfloat16*)(g_wt_hi + off) = h;
    *(__nv_bfloat16*)(g_wt_lo + off) = l;
}

// ---------------------------------------------------------------- init activations
__global__ void init_act(const float* __restrict__ x, float* __restrict__ dout) {
    int g = blockIdx.x * blockDim.x + threadIdx.x;   // 1024 rows * 512 groups
    int row = g >> 9;
    int k0 = (g & 511) * 8;
    if ((g & 511) == 0) g_scale[row] = 1.0f;         // step-0 hid scale (hid = 0)
    size_t off = act_off(row, k0);
    if (k0 < IN_DIM) {
        float4 a = *(const float4*)(x + (size_t)row * IN_DIM + k0);
        float4 b = *(const float4*)(x + (size_t)row * IN_DIM + k0 + 4);
        *(float4*)(dout + (size_t)row * L_DIM + k0)     = a;
        *(float4*)(dout + (size_t)row * L_DIM + k0 + 4) = b;
        float f[8] = {a.x, a.y, a.z, a.w, b.x, b.y, b.z, b.w};
        uint4 H, L;
        split8(f, H, L);
        *(uint4*)(g_act_hi + off) = H;
        *(uint4*)(g_act_lo + off) = L;
        *(uint4*)(g_act_hi + ACT_BUF + off) = H;
        *(uint4*)(g_act_lo + ACT_BUF + off) = L;
    } else {
        uint4 z = make_uint4(0, 0, 0, 0);
        *(uint4*)(g_act_hi + off) = z;
        *(uint4*)(g_act_lo + off) = z;
    }
}

// ---------------------------------------------------------------- GEMM step
// 256 threads, warp grid 2(M)x4(N), warp tile 64x48, KC=64, 2-stage bulk pipe.
// Chunk order: hid chunks (32..63) first, then acc *= s_row, then chunks 0..31.
__global__ __launch_bounds__(256, 1)
void gemm_step(float* __restrict__ dout, int step) {
    extern __shared__ __align__(1024) char smem[];
    const uint32_t sb = s2u(smem);
    const int tid = threadIdx.x, warp = tid >> 5, lane = tid & 31;
    const int ntile = blockIdx.x, mtile = blockIdx.y;
    const int buf = step & 1;
    const bool last = (step == NSTEPS - 1);

    const char* srcAh = g_act_hi + (size_t)buf * ACT_BUF + (size_t)mtile * NKC * ABLK;
    const char* srcAl = g_act_lo + (size_t)buf * ACT_BUF + (size_t)mtile * NKC * ABLK;
    const char* srcBh = g_wt_hi + (size_t)ntile * NKC * BBLK;
    const char* srcBl = g_wt_lo + (size_t)ntile * NKC * BBLK;

    const uint32_t mb = sb + SMEM_DATA;
    if (tid == 0) {
        mbar_init(mb, 1);
        mbar_init(mb + 8, 1);
    }
    __syncthreads();

    // prologue: permuted chunks 0,1 -> hid chunks 32,33
    if (tid == 0) {
        #pragma unroll
        for (int c = 0; c < NSTG; c++) {
            const int ck = 32 + c;
            uint32_t st = sb + c * STAGE;
            mbar_expect_tx(mb + 8 * c, STAGE);
            bulk_g2s(st,                   srcAh + (size_t)ck * ABLK, ABLK, mb + 8 * c);
            bulk_g2s(st + ABLK,            srcAl + (size_t)ck * ABLK, ABLK, mb + 8 * c);
            bulk_g2s(st + 2 * ABLK,        srcBh + (size_t)ck * BBLK, BBLK, mb + 8 * c);
            bulk_g2s(st + 2 * ABLK + BBLK, srcBl + (size_t)ck * BBLK, BBLK, mb + 8 * c);
        }
    }

    // fragment smem offsets (4 k16-steps per chunk)
    const int m0 = (warp >> 2) * 64;
    const int n0 = (warp & 3) * 48;
    uint32_t aOff[4][4], bOff[3][4];
    #pragma unroll
    for (int mi = 0; mi < 4; mi++)
        #pragma unroll
        for (int ks = 0; ks < 4; ks++) {
            int row = m0 + mi * 16 + (lane & 15);
            int col = ks * 32 + (lane >> 4) * 16;
            aOff[mi][ks] = swz128((uint32_t)(row * ROWB + col));
        }
    #pragma unroll
    for (int nb = 0; nb < 3; nb++)
        #pragma unroll
        for (int ks = 0; ks < 4; ks++) {
            int grp = lane >> 3;
            int row = n0 + nb * 16 + ((grp & 2) << 2) + (lane & 7);
            int col = ks * 32 + (grp & 1) * 16;
            bOff[nb][ks] = swz128((uint32_t)(row * ROWB + col));
        }

    float acc[4][6][4];
    #pragma unroll
    for (int mi = 0; mi < 4; mi++)
        #pragma unroll
        for (int ni = 0; ni < 6; ni++)
            #pragma unroll
            for (int q = 0; q < 4; q++) acc[mi][ni][q] = 0.0f;

    // mainloop (permuted): i<32 -> chunk 32+i (hid), i>=32 -> chunk i-32 (x+out)
    for (int i = 0; i < NKC; i++) {
        const int st = i & 1;
        mbar_wait(mb + 8 * st, (uint32_t)((i >> 1) & 1));

        const uint32_t aHiB = sb + st * STAGE;
        const uint32_t aLoB = aHiB + ABLK;
        const uint32_t bHiB = aHiB + 2 * ABLK;
        const uint32_t bLoB = bHiB + BBLK;

        #pragma unroll
        for (int ks = 0; ks < 4; ks++) {
            uint32_t ah[4][4], al[4][4], bh[6][2], bl[6][2];
            #pragma unroll
            for (int mi = 0; mi < 4; mi++) {
                ldsm4(ah[mi], aHiB + aOff[mi][ks]);
                ldsm4(al[mi], aLoB + aOff[mi][ks]);
            }
            #pragma unroll
            for (int nb = 0; nb < 3; nb++) {
                uint32_t t[4];
                ldsm4(t, bHiB + bOff[nb][ks]);
                bh[2*nb][0] = t[0]; bh[2*nb][1] = t[1];
                bh[2*nb+1][0] = t[2]; bh[2*nb+1][1] = t[3];
                ldsm4(t, bLoB + bOff[nb][ks]);
                bl[2*nb][0] = t[0]; bl[2*nb][1] = t[1];
                bl[2*nb+1][0] = t[2]; bl[2*nb+1][1] = t[3];
            }
            #pragma unroll
            for (int mi = 0; mi < 4; mi++)
                #pragma unroll
                for (int ni = 0; ni < 6; ni++) {
                    mma16816(acc[mi][ni], ah[mi], bh[ni]);
                    mma16816(acc[mi][ni], ah[mi], bl[ni]);
                    mma16816(acc[mi][ni], al[mi], bh[ni]);
                }
        }

        // after all hid chunks: fold in the deferred row-normalization scale
        if (i == 31) {
            #pragma unroll
            for (int mi = 0; mi < 4; mi++) {
                #pragma unroll
                for (int h = 0; h < 2; h++) {
                    const int row = mtile * MT + m0 + mi * 16 + (lane >> 2) + h * 8;
                    const float s = __ldg(&g_scale[row]);
                    #pragma unroll
                    for (int ni = 0; ni < 6; ni++) {
                        acc[mi][ni][2*h]   *= s;
                        acc[mi][ni][2*h+1] *= s;
                    }
                }
            }
        }

        __syncthreads();
        const int iN = i + NSTG;
        if (tid == 0 && iN < NKC) {
            const int ck = (iN < 32) ? (32 + iN) : (iN - 32);
            uint32_t stB = sb + st * STAGE;
            mbar_expect_tx(mb + 8 * st, STAGE);
            bulk_g2s(stB,                   srcAh + (size_t)ck * ABLK, ABLK, mb + 8 * st);
            bulk_g2s(stB + ABLK,            srcAl + (size_t)ck * ABLK, ABLK, mb + 8 * st);
            bulk_g2s(stB + 2 * ABLK,        srcBh + (size_t)ck * BBLK, BBLK, mb + 8 * st);
            bulk_g2s(stB + 2 * ABLK + BBLK, srcBl + (size_t)ck * BBLK, BBLK, mb + 8 * st);
        }
    }

    // epilogue: relu; last -> fp32 to dout; else bf16 hi/lo to next act buffer
    char* dHi = g_act_hi + (size_t)(1 - buf) * ACT_BUF;
    char* dLo = g_act_lo + (size_t)(1 - buf) * ACT_BUF;
    #pragma unroll
    for (int mi = 0; mi < 4; mi++) {
        const int r0 = mtile * MT + m0 + mi * 16 + (lane >> 2);
        #pragma unroll
        for (int ni = 0; ni < 6; ni++) {
            const int n = ntile * NT + n0 + ni * 8 + (lane & 3) * 2;
            #pragma unroll
            for (int h = 0; h < 2; h++) {
                const int row = r0 + h * 8;
                float v0 = fmaxf(acc[mi][ni][2*h],   0.0f);
                float v1 = fmaxf(acc[mi][ni][2*h+1], 0.0f);
                if (last) {
                    *(float2*)(dout + (size_t)row * L_DIM + IN_DIM + n) = make_float2(v0, v1);
                } else {
                    uint32_t H, L;
                    split2(v0, v1, H, L);
                    size_t off = act_off(row, IN_DIM + n);
                    *(uint32_t*)(dHi + off) = H;
                    *(uint32_t*)(dLo + off) = L;
                }
            }
        }
    }
}

// ---------------------------------------------------------------- scale compute
// Reads the just-written act buffer's hid cols, computes s_row = 1/max(||hid||,EPS).
// No activation rewrite: the scale is applied inside the NEXT gemm_step.
__global__ __launch_bounds__(256)
void compute_scale(int step) {
    const int row = blockIdx.x, t = threadIdx.x;
    const int nbuf = 1 - (step & 1);
    size_t aOff = (size_t)nbuf * ACT_BUF + act_off(row, IN_DIM + OUT_DIM + t * 8);
    uint4 H = *(uint4*)(g_act_hi + aOff);
    uint4 L = *(uint4*)(g_act_lo + aOff);
    const uint32_t* hw = &H.x;
    const uint32_t* lw = &L.x;
    float ss = 0.0f;
    #pragma unroll
    for (int p = 0; p < 4; p++) {
        float f0 = rc2(hw[p], 0) + rc2(lw[p], 0);
        float f1 = rc2(hw[p], 1) + rc2(lw[p], 1);
        ss += f0 * f0 + f1 * f1;
    }
    __shared__ float red[8];
    #pragma unroll
    for (int off = 16; off > 0; off >>= 1) ss += __shfl_xor_sync(0xFFFFFFFFu, ss, off);
    if ((t & 31) == 0) red[t >> 5] = ss;
    __syncthreads();
    if (t == 0) {
        float tot = 0.0f;
        #pragma unroll
        for (int w = 0; w < 8; w++) tot += red[w];
        g_scale[row] = 1.0f / fmaxf(sqrtf(tot), EPS_N);
    }
}

// ---------------------------------------------------------------- final normalize (fp32, dout)
__global__ __launch_bounds__(256)
void final_norm(float* __restrict__ dout) {
    const int row = blockIdx.x, t = threadIdx.x;
    float* hid = dout + (size_t)row * L_DIM + IN_DIM + OUT_DIM;
    float4 v0 = *(float4*)(hid + t * 8);
    float4 v1 = *(float4*)(hid + t * 8 + 4);
    float ss = v0.x*v0.x + v0.y*v0.y + v0.z*v0.z + v0.w*v0.w
             + v1.x*v1.x + v1.y*v1.y + v1.z*v1.z + v1.w*v1.w;
    __shared__ float red[8];
    __shared__ float s_scale;
    #pragma unroll
    for (int off = 16; off > 0; off >>= 1) ss += __shfl_xor_sync(0xFFFFFFFFu, ss, off);
    if ((t & 31) == 0) red[t >> 5] = ss;
    __syncthreads();
    if (t == 0) {
        float tot = 0.0f;
        #pragma unroll
        for (int w = 0; w < 8; w++) tot += red[w];
        s_scale = 1.0f / fmaxf(sqrtf(tot), EPS_N);
    }
    __syncthreads();
    const float sc = s_scale;
    v0.x *= sc; v0.y *= sc; v0.z *= sc; v0.w *= sc;
    v1.x *= sc; v1.y *= sc; v1.z *= sc; v1.w *= sc;
    *(float4*)(hid + t * 8)     = v0;
    *(float4*)(hid + t * 8 + 4) = v1;
}

// ---------------------------------------------------------------- launch
extern "C" void kernel_launch(void* const* d_in, const int* in_sizes, int n_in,
                              void* d_out, int out_size) {
    const float* x = (const float*)d_in[0];
    const float* W = (const float*)d_in[2];
    const float* A = (const float*)d_in[3];
    float* out = (float*)d_out;

    cudaFuncSetAttribute(gemm_step, cudaFuncAttributeMaxDynamicSharedMemorySize, SMEM_TOT);

    prep_w<<<dim3(L_DIM / 32, NCOLS / 32), dim3(32, 32)>>>(W, A);
    init_act<<<(B_DIM * 512) / 256, 256>>>(x, out);

    for (int s = 0; s < NSTEPS; s++) {
        gemm_step<<<dim3(NTILES, MTILES), 256, SMEM_TOT>>>(out, s);
        if (s < NSTEPS - 1)
            compute_scale<<<B_DIM, 256>>>(s);
        else
            final_norm<<<B_DIM, 256>>>(out);
    }
}

// round 11
// speedup vs baseline: 5.4796x; 1.0527x over previous
#include <cuda_runtime.h>
#include <cuda_bf16.h>
#include <stdint.h>
#include <math.h>

// ---------------------------------------------------------------- constants
#define IN_DIM   1024
#define OUT_DIM  1024
#define L_DIM    4096
#define B_DIM    1024
#define NCOLS    3072
#define NSTEPS   32
#define EPS_N    1e-12f

// GEMM: C(M=1024, N=3072, K=4096). CTA 128x192, K-chunk 64.
#define MT       128
#define NT       192
#define KC       64
#define NKC      64
#define MTILES   8
#define NTILES   16            // grid 16x8 = 128 CTAs (one wave)

#define ROWB     128           // bytes per row (64 bf16) - SW128 atom
#define ABLK     (MT*ROWB)     // 16384
#define BBLK     (NT*ROWB)     // 24576
#define STAGE    (2*ABLK + 2*BBLK)   // 81920
#define NSTG     2
#define SMEM_DATA (NSTG*STAGE)       // 163840
#define SMEM_TOT  (SMEM_DATA + 64)

#define ACT_BUF  ((size_t)MTILES * NKC * ABLK)   // 8 MB per buffer
#define WT_TOT   ((size_t)NTILES * NKC * BBLK)   // 24 MB

// ---------------------------------------------------------------- device scratch
__device__ __align__(1024) char g_wt_hi[WT_TOT];
__device__ __align__(1024) char g_wt_lo[WT_TOT];
__device__ __align__(1024) char g_act_hi[2 * ACT_BUF];
__device__ __align__(1024) char g_act_lo[2 * ACT_BUF];
__device__ float g_scale[B_DIM];

// ---------------------------------------------------------------- helpers
__device__ __forceinline__ uint32_t swz128(uint32_t b) { return b ^ ((b >> 3) & 0x70u); }

__device__ __forceinline__ uint32_t s2u(const void* p) {
    uint32_t a;
    asm("{ .reg .u64 t; cvta.to.shared.u64 t, %1; cvt.u32.u64 %0, t; }" : "=r"(a) : "l"(p));
    return a;
}
__device__ __forceinline__ void mbar_init(uint32_t a, uint32_t c) {
    asm volatile("mbarrier.init.shared.b64 [%0], %1;" :: "r"(a), "r"(c) : "memory");
}
__device__ __forceinline__ void mbar_expect_tx(uint32_t a, uint32_t bytes) {
    asm volatile("mbarrier.arrive.expect_tx.shared.b64 _, [%0], %1;" :: "r"(a), "r"(bytes) : "memory");
}
__device__ __forceinline__ void mbar_arrive(uint32_t a) {
    asm volatile("mbarrier.arrive.shared.b64 _, [%0];" :: "r"(a) : "memory");
}
__device__ __forceinline__ void mbar_wait(uint32_t a, uint32_t par) {
    asm volatile("{\n\t.reg .pred P;\n\tWL_%=:\n\t"
                 "mbarrier.try_wait.parity.acquire.cta.shared::cta.b64 P, [%0], %1, 0x989680;\n\t"
                 "@P bra.uni WD_%=;\n\tbra.uni WL_%=;\n\tWD_%=:\n\t}"
                 :: "r"(a), "r"(par) : "memory");
}
__device__ __forceinline__ void bulk_g2s(uint32_t dst, const void* src, uint32_t bytes, uint32_t mbar) {
    asm volatile("cp.async.bulk.shared::cluster.global.mbarrier::complete_tx::bytes [%0], [%1], %2, [%3];"
                 :: "r"(dst), "l"(src), "r"(bytes), "r"(mbar) : "memory");
}
__device__ __forceinline__ void ldsm4(uint32_t* r, uint32_t addr) {
    asm volatile("ldmatrix.sync.aligned.m8n8.x4.shared.b16 {%0,%1,%2,%3}, [%4];"
                 : "=r"(r[0]), "=r"(r[1]), "=r"(r[2]), "=r"(r[3]) : "r"(addr));
}
__device__ __forceinline__ void mma16816(float* c, const uint32_t* a, const uint32_t* b) {
    asm volatile("mma.sync.aligned.m16n8k16.row.col.f32.bf16.bf16.f32 "
                 "{%0,%1,%2,%3}, {%4,%5,%6,%7}, {%8,%9}, {%0,%1,%2,%3};"
                 : "+f"(c[0]), "+f"(c[1]), "+f"(c[2]), "+f"(c[3])
                 : "r"(a[0]), "r"(a[1]), "r"(a[2]), "r"(a[3]), "r"(b[0]), "r"(b[1]));
}

__device__ __forceinline__ void split2(float f0, float f1, uint32_t& H, uint32_t& L) {
    __nv_bfloat16 h0 = __float2bfloat16_rn(f0);
    __nv_bfloat16 h1 = __float2bfloat16_rn(f1);
    __nv_bfloat16 l0 = __float2bfloat16_rn(f0 - __bfloat162float(h0));
    __nv_bfloat16 l1 = __float2bfloat16_rn(f1 - __bfloat162float(h1));
    H = (uint32_t)__bfloat16_as_ushort(h0) | ((uint32_t)__bfloat16_as_ushort(h1) << 16);
    L = (uint32_t)__bfloat16_as_ushort(l0) | ((uint32_t)__bfloat16_as_ushort(l1) << 16);
}
__device__ __forceinline__ void split8(const float* f, uint4& H, uint4& L) {
    uint32_t hw[4], lw[4];
    #pragma unroll
    for (int p = 0; p < 4; p++) split2(f[2*p], f[2*p+1], hw[p], lw[p]);
    H = make_uint4(hw[0], hw[1], hw[2], hw[3]);
    L = make_uint4(lw[0], lw[1], lw[2], lw[3]);
}
__device__ __forceinline__ float rc2(uint32_t w, int hi) {
    return __bfloat162float(__ushort_as_bfloat16((unsigned short)(hi ? (w >> 16) : (w & 0xFFFFu))));
}

// act tiled address: global row (0..1023), act k-index (0..4095)
__device__ __forceinline__ size_t act_off(int row, int k) {
    int mtile = row >> 7, rin = row & 127;
    int chunk = k >> 6,  cc = k & 63;
    return (size_t)(mtile * NKC + chunk) * ABLK + swz128((uint32_t)(rin * ROWB + cc * 2));
}

// ---------------------------------------------------------------- prep weights
__global__ void prep_w(const float* __restrict__ W, const float* __restrict__ A) {
    __shared__ float tile[32][33];
    const int i0 = blockIdx.y * 32, j0 = blockIdx.x * 32;
    const int tx = threadIdx.x, ty = threadIdx.y;
    tile[ty][tx] = A[(size_t)(j0 + ty) * L_DIM + (IN_DIM + i0 + tx)];
    __syncthreads();
    const int i = i0 + ty, j = j0 + tx;
    float v = W[(size_t)(IN_DIM + i) * L_DIM + j] * tile[tx][ty];
    __nv_bfloat16 h = __float2bfloat16_rn(v);
    __nv_bfloat16 l = __float2bfloat16_rn(v - __bfloat162float(h));
    const int ntile = i / NT, r = i % NT;
    const int chunk = j >> 6, cc = j & 63;
    size_t off = (size_t)(ntile * NKC + chunk) * BBLK + swz128((uint32_t)(r * ROWB + cc * 2));
    *(__nv_bfloat16*)(g_wt_hi + off) = h;
    *(__nv_bfloat16*)(g_wt_lo + off) = l;
}

// ---------------------------------------------------------------- init activations
__global__ void init_act(const float* __restrict__ x, float* __restrict__ dout) {
    int g = blockIdx.x * blockDim.x + threadIdx.x;
    int row = g >> 9;
    int k0 = (g & 511) * 8;
    if ((g & 511) == 0) g_scale[row] = 1.0f;
    size_t off = act_off(row, k0);
    if (k0 < IN_DIM) {
        float4 a = *(const float4*)(x + (size_t)row * IN_DIM + k0);
        float4 b = *(const float4*)(x + (size_t)row * IN_DIM + k0 + 4);
        *(float4*)(dout + (size_t)row * L_DIM + k0)     = a;
        *(float4*)(dout + (size_t)row * L_DIM + k0 + 4) = b;
        float f[8] = {a.x, a.y, a.z, a.w, b.x, b.y, b.z, b.w};
        uint4 H, L;
        split8(f, H, L);
        *(uint4*)(g_act_hi + off) = H;
        *(uint4*)(g_act_lo + off) = L;
        *(uint4*)(g_act_hi + ACT_BUF + off) = H;
        *(uint4*)(g_act_lo + ACT_BUF + off) = L;
    } else {
        uint4 z = make_uint4(0, 0, 0, 0);
        *(uint4*)(g_act_hi + off) = z;
        *(uint4*)(g_act_lo + off) = z;
    }
}

// ---------------------------------------------------------------- GEMM step
// 288 threads: warps 0-7 compute (2x4 grid, 64x48 tiles), warp 8 producer.
// 2-stage bulk pipe with full/empty mbarriers; NO __syncthreads in mainloop.
// Chunk order: hid chunks (32..63) first, fold s_row, then chunks 0..31.
__global__ __launch_bounds__(288, 1)
void gemm_step(float* __restrict__ dout, int step) {
    extern __shared__ __align__(1024) char smem[];
    const uint32_t sb = s2u(smem);
    const int tid = threadIdx.x, warp = tid >> 5, lane = tid & 31;
    const int ntile = blockIdx.x, mtile = blockIdx.y;
    const int buf = step & 1;
    const bool last = (step == NSTEPS - 1);

    const char* srcAh = g_act_hi + (size_t)buf * ACT_BUF + (size_t)mtile * NKC * ABLK;
    const char* srcAl = g_act_lo + (size_t)buf * ACT_BUF + (size_t)mtile * NKC * ABLK;
    const char* srcBh = g_wt_hi + (size_t)ntile * NKC * BBLK;
    const char* srcBl = g_wt_lo + (size_t)ntile * NKC * BBLK;

    const uint32_t mbF = sb + SMEM_DATA;       // full[0], full[1]
    const uint32_t mbE = sb + SMEM_DATA + 16;  // empty[0], empty[1]
    if (tid == 0) {
        mbar_init(mbF, 1);     mbar_init(mbF + 8, 1);
        mbar_init(mbE, 8);     mbar_init(mbE + 8, 8);
    }
    __syncthreads();

    if (warp == 8) {
        // ---------------- producer warp (lane 0 only)
        if (lane == 0) {
            for (int c = 0; c < NKC; c++) {
                const int st = c & 1;
                if (c >= NSTG) mbar_wait(mbE + 8 * st, (uint32_t)(((c >> 1) - 1) & 1));
                const int ck = (c < 32) ? (32 + c) : (c - 32);   // hid chunks first
                uint32_t stB = sb + st * STAGE;
                mbar_expect_tx(mbF + 8 * st, STAGE);
                bulk_g2s(stB,                   srcAh + (size_t)ck * ABLK, ABLK, mbF + 8 * st);
                bulk_g2s(stB + ABLK,            srcAl + (size_t)ck * ABLK, ABLK, mbF + 8 * st);
                bulk_g2s(stB + 2 * ABLK,        srcBh + (size_t)ck * BBLK, BBLK, mbF + 8 * st);
                bulk_g2s(stB + 2 * ABLK + BBLK, srcBl + (size_t)ck * BBLK, BBLK, mbF + 8 * st);
            }
        }
        return;
    }

    // ---------------- compute warps 0..7
    const int m0 = (warp >> 2) * 64;
    const int n0 = (warp & 3) * 48;
    uint32_t aOff[4][4], bOff[3][4];
    #pragma unroll
    for (int mi = 0; mi < 4; mi++)
        #pragma unroll
        for (int ks = 0; ks < 4; ks++) {
            int row = m0 + mi * 16 + (lane & 15);
            int col = ks * 32 + (lane >> 4) * 16;
            aOff[mi][ks] = swz128((uint32_t)(row * ROWB + col));
        }
    #pragma unroll
    for (int nb = 0; nb < 3; nb++)
        #pragma unroll
        for (int ks = 0; ks < 4; ks++) {
            int grp = lane >> 3;
            int row = n0 + nb * 16 + ((grp & 2) << 2) + (lane & 7);
            int col = ks * 32 + (grp & 1) * 16;
            bOff[nb][ks] = swz128((uint32_t)(row * ROWB + col));
        }

    float acc[4][6][4];
    #pragma unroll
    for (int mi = 0; mi < 4; mi++)
        #pragma unroll
        for (int ni = 0; ni < 6; ni++)
            #pragma unroll
            for (int q = 0; q < 4; q++) acc[mi][ni][q] = 0.0f;

    for (int i = 0; i < NKC; i++) {
        const int st = i & 1;
        mbar_wait(mbF + 8 * st, (uint32_t)((i >> 1) & 1));

        const uint32_t aHiB = sb + st * STAGE;
        const uint32_t aLoB = aHiB + ABLK;
        const uint32_t bHiB = aHiB + 2 * ABLK;
        const uint32_t bLoB = bHiB + BBLK;

        #pragma unroll
        for (int ks = 0; ks < 4; ks++) {
            uint32_t ah[4][4], al[4][4], bh[6][2], bl[6][2];
            #pragma unroll
            for (int mi = 0; mi < 4; mi++) {
                ldsm4(ah[mi], aHiB + aOff[mi][ks]);
                ldsm4(al[mi], aLoB + aOff[mi][ks]);
            }
            #pragma unroll
            for (int nb = 0; nb < 3; nb++) {
                uint32_t t[4];
                ldsm4(t, bHiB + bOff[nb][ks]);
                bh[2*nb][0] = t[0]; bh[2*nb][1] = t[1];
                bh[2*nb+1][0] = t[2]; bh[2*nb+1][1] = t[3];
                ldsm4(t, bLoB + bOff[nb][ks]);
                bl[2*nb][0] = t[0]; bl[2*nb][1] = t[1];
                bl[2*nb+1][0] = t[2]; bl[2*nb+1][1] = t[3];
            }
            #pragma unroll
            for (int mi = 0; mi < 4; mi++)
                #pragma unroll
                for (int ni = 0; ni < 6; ni++) {
                    mma16816(acc[mi][ni], ah[mi], bh[ni]);
                    mma16816(acc[mi][ni], ah[mi], bl[ni]);
                    mma16816(acc[mi][ni], al[mi], bh[ni]);
                }
        }

        // all LDSMs for this stage done -> release it to the producer
        if (lane == 0) mbar_arrive(mbE + 8 * st);

        // after all hid chunks: fold deferred row-normalization scale
        if (i == 31) {
            #pragma unroll
            for (int mi = 0; mi < 4; mi++) {
                #pragma unroll
                for (int h = 0; h < 2; h++) {
                    const int row = mtile * MT + m0 + mi * 16 + (lane >> 2) + h * 8;
                    const float s = __ldg(&g_scale[row]);
                    #pragma unroll
                    for (int ni = 0; ni < 6; ni++) {
                        acc[mi][ni][2*h]   *= s;
                        acc[mi][ni][2*h+1] *= s;
                    }
                }
            }
        }
    }

    // epilogue
    char* dHi = g_act_hi + (size_t)(1 - buf) * ACT_BUF;
    char* dLo = g_act_lo + (size_t)(1 - buf) * ACT_BUF;
    #pragma unroll
    for (int mi = 0; mi < 4; mi++) {
        const int r0 = mtile * MT + m0 + mi * 16 + (lane >> 2);
        #pragma unroll
        for (int ni = 0; ni < 6; ni++) {
            const int n = ntile * NT + n0 + ni * 8 + (lane & 3) * 2;
            #pragma unroll
            for (int h = 0; h < 2; h++) {
                const int row = r0 + h * 8;
                float v0 = fmaxf(acc[mi][ni][2*h],   0.0f);
                float v1 = fmaxf(acc[mi][ni][2*h+1], 0.0f);
                if (last) {
                    *(float2*)(dout + (size_t)row * L_DIM + IN_DIM + n) = make_float2(v0, v1);
                } else {
                    uint32_t H, L;
                    split2(v0, v1, H, L);
                    size_t off = act_off(row, IN_DIM + n);
                    *(uint32_t*)(dHi + off) = H;
                    *(uint32_t*)(dLo + off) = L;
                }
            }
        }
    }
}

// ---------------------------------------------------------------- scale compute
__global__ __launch_bounds__(256)
void compute_scale(int step) {
    const int row = blockIdx.x, t = threadIdx.x;
    const int nbuf = 1 - (step & 1);
    size_t aOff = (size_t)nbuf * ACT_BUF + act_off(row, IN_DIM + OUT_DIM + t * 8);
    uint4 H = *(uint4*)(g_act_hi + aOff);
    uint4 L = *(uint4*)(g_act_lo + aOff);
    const uint32_t* hw = &H.x;
    const uint32_t* lw = &L.x;
    float ss = 0.0f;
    #pragma unroll
    for (int p = 0; p < 4; p++) {
        float f0 = rc2(hw[p], 0) + rc2(lw[p], 0);
        float f1 = rc2(hw[p], 1) + rc2(lw[p], 1);
        ss += f0 * f0 + f1 * f1;
    }
    __shared__ float red[8];
    #pragma unroll
    for (int off = 16; off > 0; off >>= 1) ss += __shfl_xor_sync(0xFFFFFFFFu, ss, off);
    if ((t & 31) == 0) red[t >> 5] = ss;
    __syncthreads();
    if (t == 0) {
        float tot = 0.0f;
        #pragma unroll
        for (int w = 0; w < 8; w++) tot += red[w];
        g_scale[row] = 1.0f / fmaxf(sqrtf(tot), EPS_N);
    }
}

// ---------------------------------------------------------------- final normalize
__global__ __launch_bounds__(256)
void final_norm(float* __restrict__ dout) {
    const int row = blockIdx.x, t = threadIdx.x;
    float* hid = dout + (size_t)row * L_DIM + IN_DIM + OUT_DIM;
    float4 v0 = *(float4*)(hid + t * 8);
    float4 v1 = *(float4*)(hid + t * 8 + 4);
    float ss = v0.x*v0.x + v0.y*v0.y + v0.z*v0.z + v0.w*v0.w
             + v1.x*v1.x + v1.y*v1.y + v1.z*v1.z + v1.w*v1.w;
    __shared__ float red[8];
    __shared__ float s_scale;
    #pragma unroll
    for (int off = 16; off > 0; off >>= 1) ss += __shfl_xor_sync(0xFFFFFFFFu, ss, off);
    if ((t & 31) == 0) red[t >> 5] = ss;
    __syncthreads();
    if (t == 0) {
        float tot = 0.0f;
        #pragma unroll
        for (int w = 0; w < 8; w++) tot += red[w];
        s_scale = 1.0f / fmaxf(sqrtf(tot), EPS_N);
    }
    __syncthreads();
    const float sc = s_scale;
    v0.x *= sc; v0.y *= sc; v0.z *= sc; v0.w *= sc;
    v1.x *= sc; v1.y *= sc; v1.z *= sc; v1.w *= sc;
    *(float4*)(hid + t * 8)     = v0;
    *(float4*)(hid + t * 8 + 4) = v1;
}

// ---------------------------------------------------------------- launch
extern "C" void kernel_launch(void* const* d_in, const int* in_sizes, int n_in,
                              void* d_out, int out_size) {
    const float* x = (const float*)d_in[0];
    const float* W = (const float*)d_in[2];
    const float* A = (const float*)d_in[3];
    float* out = (float*)d_out;

    cudaFuncSetAttribute(gemm_step, cudaFuncAttributeMaxDynamicSharedMemorySize, SMEM_TOT);

    prep_w<<<dim3(L_DIM / 32, NCOLS / 32), dim3(32, 32)>>>(W, A);
    init_act<<<(B_DIM * 512) / 256, 256>>>(x, out);

    for (int s = 0; s < NSTEPS; s++) {
        gemm_step<<<dim3(NTILES, MTILES), 288, SMEM_TOT>>>(out, s);
        if (s < NSTEPS - 1)
            compute_scale<<<B_DIM, 256>>>(s);
        else
            final_norm<<<B_DIM, 256>>>(out);
    }
}

// round 14
// speedup vs baseline: 5.6113x; 1.0240x over previous
#include <cuda_runtime.h>
#include <cuda_bf16.h>
#include <stdint.h>
#include <math.h>

// ---------------------------------------------------------------- constants
#define IN_DIM   1024
#define OUT_DIM  1024
#define L_DIM    4096
#define B_DIM    1024
#define NCOLS    3072
#define NSTEPS   32
#define EPS_N    1e-12f

// GEMM: C(M=1024, N=3072, K=4096). CTA 128x192, K-chunk 64.
#define MT       128
#define NT       192
#define KC       64
#define NKC      64
#define MTILES   8
#define NTILES   16            // grid 16x8 = 128 CTAs (one wave)

#define ROWB     128           // bytes per row (64 bf16) - SW128 atom
#define ABLK     (MT*ROWB)     // 16384
#define BBLK     (NT*ROWB)     // 24576
#define STAGE    (2*ABLK + 2*BBLK)   // 81920
#define NSTG     2
#define SMEM_DATA (NSTG*STAGE)       // 163840
// after data: mbarriers (32B pad to 64), s_smem (512B), spart (2048B)
#define SM_MBAR   SMEM_DATA
#define SM_SSCALE (SMEM_DATA + 64)
#define SM_SPART  (SMEM_DATA + 64 + 512)
#define SMEM_TOT  (SMEM_DATA + 64 + 512 + 2048)

#define ACT_BUF  ((size_t)MTILES * NKC * ABLK)   // 8 MB per buffer
#define WT_TOT   ((size_t)NTILES * NKC * BBLK)   // 24 MB

// hid cols are n >= 1024 -> ntiles 5..15 contribute (tile 5 partially)
#define PART_T0  5
#define NPART    11

// ---------------------------------------------------------------- device scratch
__device__ __align__(1024) char g_wt_hi[WT_TOT];
__device__ __align__(1024) char g_wt_lo[WT_TOT];
__device__ __align__(1024) char g_act_hi[2 * ACT_BUF];
__device__ __align__(1024) char g_act_lo[2 * ACT_BUF];
__device__ float g_part[NPART][B_DIM];     // per-(ntile,row) hid sum-of-squares partials

// ---------------------------------------------------------------- helpers
__device__ __forceinline__ uint32_t swz128(uint32_t b) { return b ^ ((b >> 3) & 0x70u); }

__device__ __forceinline__ uint32_t s2u(const void* p) {
    uint32_t a;
    asm("{ .reg .u64 t; cvta.to.shared.u64 t, %1; cvt.u32.u64 %0, t; }" : "=r"(a) : "l"(p));
    return a;
}
__device__ __forceinline__ void mbar_init(uint32_t a, uint32_t c) {
    asm volatile("mbarrier.init.shared.b64 [%0], %1;" :: "r"(a), "r"(c) : "memory");
}
__device__ __forceinline__ void mbar_expect_tx(uint32_t a, uint32_t bytes) {
    asm volatile("mbarrier.arrive.expect_tx.shared.b64 _, [%0], %1;" :: "r"(a), "r"(bytes) : "memory");
}
__device__ __forceinline__ void mbar_arrive(uint32_t a) {
    asm volatile("mbarrier.arrive.shared.b64 _, [%0];" :: "r"(a) : "memory");
}
__device__ __forceinline__ void mbar_wait(uint32_t a, uint32_t par) {
    asm volatile("{\n\t.reg .pred P;\n\tWL_%=:\n\t"
                 "mbarrier.try_wait.parity.acquire.cta.shared::cta.b64 P, [%0], %1, 0x989680;\n\t"
                 "@P bra.uni WD_%=;\n\tbra.uni WL_%=;\n\tWD_%=:\n\t}"
                 :: "r"(a), "r"(par) : "memory");
}
__device__ __forceinline__ void bulk_g2s(uint32_t dst, const void* src, uint32_t bytes, uint32_t mbar) {
    asm volatile("cp.async.bulk.shared::cluster.global.mbarrier::complete_tx::bytes [%0], [%1], %2, [%3];"
                 :: "r"(dst), "l"(src), "r"(bytes), "r"(mbar) : "memory");
}
__device__ __forceinline__ void ldsm4(uint32_t* r, uint32_t addr) {
    asm volatile("ldmatrix.sync.aligned.m8n8.x4.shared.b16 {%0,%1,%2,%3}, [%4];"
                 : "=r"(r[0]), "=r"(r[1]), "=r"(r[2]), "=r"(r[3]) : "r"(addr));
}
__device__ __forceinline__ void mma16816(float* c, const uint32_t* a, const uint32_t* b) {
    asm volatile("mma.sync.aligned.m16n8k16.row.col.f32.bf16.bf16.f32 "
                 "{%0,%1,%2,%3}, {%4,%5,%6,%7}, {%8,%9}, {%0,%1,%2,%3};"
                 : "+f"(c[0]), "+f"(c[1]), "+f"(c[2]), "+f"(c[3])
                 : "r"(a[0]), "r"(a[1]), "r"(a[2]), "r"(a[3]), "r"(b[0]), "r"(b[1]));
}

__device__ __forceinline__ void split2(float f0, float f1, uint32_t& H, uint32_t& L) {
    __nv_bfloat16 h0 = __float2bfloat16_rn(f0);
    __nv_bfloat16 h1 = __float2bfloat16_rn(f1);
    __nv_bfloat16 l0 = __float2bfloat16_rn(f0 - __bfloat162float(h0));
    __nv_bfloat16 l1 = __float2bfloat16_rn(f1 - __bfloat162float(h1));
    H = (uint32_t)__bfloat16_as_ushort(h0) | ((uint32_t)__bfloat16_as_ushort(h1) << 16);
    L = (uint32_t)__bfloat16_as_ushort(l0) | ((uint32_t)__bfloat16_as_ushort(l1) << 16);
}
__device__ __forceinline__ void split8(const float* f, uint4& H, uint4& L) {
    uint32_t hw[4], lw[4];
    #pragma unroll
    for (int p = 0; p < 4; p++) split2(f[2*p], f[2*p+1], hw[p], lw[p]);
    H = make_uint4(hw[0], hw[1], hw[2], hw[3]);
    L = make_uint4(lw[0], lw[1], lw[2], lw[3]);
}

// act tiled address: global row (0..1023), act k-index (0..4095)
__device__ __forceinline__ size_t act_off(int row, int k) {
    int mtile = row >> 7, rin = row & 127;
    int chunk = k >> 6,  cc = k & 63;
    return (size_t)(mtile * NKC + chunk) * ABLK + swz128((uint32_t)(rin * ROWB + cc * 2));
}

// ---------------------------------------------------------------- prep weights
__global__ void prep_w(const float* __restrict__ W, const float* __restrict__ A) {
    __shared__ float tile[32][33];
    const int i0 = blockIdx.y * 32, j0 = blockIdx.x * 32;
    const int tx = threadIdx.x, ty = threadIdx.y;
    tile[ty][tx] = A[(size_t)(j0 + ty) * L_DIM + (IN_DIM + i0 + tx)];
    __syncthreads();
    const int i = i0 + ty, j = j0 + tx;
    float v = W[(size_t)(IN_DIM + i) * L_DIM + j] * tile[tx][ty];
    __nv_bfloat16 h = __float2bfloat16_rn(v);
    __nv_bfloat16 l = __float2bfloat16_rn(v - __bfloat162float(h));
    const int ntile = i / NT, r = i % NT;
    const int chunk = j >> 6, cc = j & 63;
    size_t off = (size_t)(ntile * NKC + chunk) * BBLK + swz128((uint32_t)(r * ROWB + cc * 2));
    *(__nv_bfloat16*)(g_wt_hi + off) = h;
    *(__nv_bfloat16*)(g_wt_lo + off) = l;
}

// ---------------------------------------------------------------- init activations
__global__ void init_act(const float* __restrict__ x, float* __restrict__ dout) {
    int g = blockIdx.x * blockDim.x + threadIdx.x;
    if (g < NPART * B_DIM) ((float*)g_part)[g] = 0.0f;   // step-0 hid partials (hid = 0)
    int row = g >> 9;
    int k0 = (g & 511) * 8;
    size_t off = act_off(row, k0);
    if (k0 < IN_DIM) {
        float4 a = *(const float4*)(x + (size_t)row * IN_DIM + k0);
        float4 b = *(const float4*)(x + (size_t)row * IN_DIM + k0 + 4);
        *(float4*)(dout + (size_t)row * L_DIM + k0)     = a;
        *(float4*)(dout + (size_t)row * L_DIM + k0 + 4) = b;
        float f[8] = {a.x, a.y, a.z, a.w, b.x, b.y, b.z, b.w};
        uint4 H, L;
        split8(f, H, L);
        *(uint4*)(g_act_hi + off) = H;
        *(uint4*)(g_act_lo + off) = L;
        *(uint4*)(g_act_hi + ACT_BUF + off) = H;
        *(uint4*)(g_act_lo + ACT_BUF + off) = L;
    } else {
        uint4 z = make_uint4(0, 0, 0, 0);
        *(uint4*)(g_act_hi + off) = z;
        *(uint4*)(g_act_lo + off) = z;
    }
}

// ---------------------------------------------------------------- GEMM step
// 288 threads: warps 0-7 compute (2x4 grid, 64x48 tiles), warp 8 producer.
// Fused hid-norm: prologue builds s_row from g_part (prev step); epilogue of
// tiles 5..15 writes this step's per-tile hid sum-of-squares partials.
__global__ __launch_bounds__(288, 1)
void gemm_step(float* __restrict__ dout, int step) {
    extern __shared__ __align__(1024) char smem[];
    const uint32_t sb = s2u(smem);
    const int tid = threadIdx.x, warp = tid >> 5, lane = tid & 31;
    const int ntile = blockIdx.x, mtile = blockIdx.y;
    const int buf = step & 1;
    const bool last = (step == NSTEPS - 1);

    const char* srcAh = g_act_hi + (size_t)buf * ACT_BUF + (size_t)mtile * NKC * ABLK;
    const char* srcAl = g_act_lo + (size_t)buf * ACT_BUF + (size_t)mtile * NKC * ABLK;
    const char* srcBh = g_wt_hi + (size_t)ntile * NKC * BBLK;
    const char* srcBl = g_wt_lo + (size_t)ntile * NKC * BBLK;

    const uint32_t mbF = sb + SM_MBAR;         // full[0], full[1]
    const uint32_t mbE = sb + SM_MBAR + 16;    // empty[0], empty[1]
    float* sScale = (float*)(smem + SM_SSCALE);          // [128]
    float* sPart  = (float*)(smem + SM_SPART);           // [4][128]
    if (tid == 0) {
        mbar_init(mbF, 1);     mbar_init(mbF + 8, 1);
        mbar_init(mbE, 8);     mbar_init(mbE + 8, 8);
    }
    __syncthreads();

    if (warp == 8) {
        // ---------------- producer warp (lane 0 only)
        if (lane == 0) {
            for (int c = 0; c < NKC; c++) {
                const int st = c & 1;
                if (c >= NSTG) mbar_wait(mbE + 8 * st, (uint32_t)(((c >> 1) - 1) & 1));
                const int ck = (c < 32) ? (32 + c) : (c - 32);   // hid chunks first
                uint32_t stB = sb + st * STAGE;
                mbar_expect_tx(mbF + 8 * st, STAGE);
                bulk_g2s(stB,                   srcAh + (size_t)ck * ABLK, ABLK, mbF + 8 * st);
                bulk_g2s(stB + ABLK,            srcAl + (size_t)ck * ABLK, ABLK, mbF + 8 * st);
                bulk_g2s(stB + 2 * ABLK,        srcBh + (size_t)ck * BBLK, BBLK, mbF + 8 * st);
                bulk_g2s(stB + 2 * ABLK + BBLK, srcBl + (size_t)ck * BBLK, BBLK, mbF + 8 * st);
            }
        }
        return;
    }

    // ---------------- compute warps 0..7
    // prologue: build s_row for this CTA's 128 rows from previous-step partials
    if (tid < MT) {
        const int grow = mtile * MT + tid;
        float ss = 0.0f;
        #pragma unroll
        for (int t = 0; t < NPART; t++) ss += g_part[t][grow];
        sScale[tid] = 1.0f / fmaxf(sqrtf(ss), EPS_N);
    }
    asm volatile("bar.sync 1, 256;" ::: "memory");

    const int m0 = (warp >> 2) * 64;
    const int n0 = (warp & 3) * 48;
    uint32_t aOff[4][4], bOff[3][4];
    #pragma unroll
    for (int mi = 0; mi < 4; mi++)
        #pragma unroll
        for (int ks = 0; ks < 4; ks++) {
            int row = m0 + mi * 16 + (lane & 15);
            int col = ks * 32 + (lane >> 4) * 16;
            aOff[mi][ks] = swz128((uint32_t)(row * ROWB + col));
        }
    #pragma unroll
    for (int nb = 0; nb < 3; nb++)
        #pragma unroll
        for (int ks = 0; ks < 4; ks++) {
            int grp = lane >> 3;
            int row = n0 + nb * 16 + ((grp & 2) << 2) + (lane & 7);
            int col = ks * 32 + (grp & 1) * 16;
            bOff[nb][ks] = swz128((uint32_t)(row * ROWB + col));
        }

    float acc[4][6][4];
    #pragma unroll
    for (int mi = 0; mi < 4; mi++)
        #pragma unroll
        for (int ni = 0; ni < 6; ni++)
            #pragma unroll
            for (int q = 0; q < 4; q++) acc[mi][ni][q] = 0.0f;

    for (int i = 0; i < NKC; i++) {
        const int st = i & 1;
        mbar_wait(mbF + 8 * st, (uint32_t)((i >> 1) & 1));

        const uint32_t aHiB = sb + st * STAGE;
        const uint32_t aLoB = aHiB + ABLK;
        const uint32_t bHiB = aHiB + 2 * ABLK;
        const uint32_t bLoB = bHiB + BBLK;

        #pragma unroll
        for (int ks = 0; ks < 4; ks++) {
            uint32_t ah[4][4], al[4][4], bh[6][2], bl[6][2];
            #pragma unroll
            for (int mi = 0; mi < 4; mi++) {
                ldsm4(ah[mi], aHiB + aOff[mi][ks]);
                ldsm4(al[mi], aLoB + aOff[mi][ks]);
            }
            #pragma unroll
            for (int nb = 0; nb < 3; nb++) {
                uint32_t t[4];
                ldsm4(t, bHiB + bOff[nb][ks]);
                bh[2*nb][0] = t[0]; bh[2*nb][1] = t[1];
                bh[2*nb+1][0] = t[2]; bh[2*nb+1][1] = t[3];
                ldsm4(t, bLoB + bOff[nb][ks]);
                bl[2*nb][0] = t[0]; bl[2*nb][1] = t[1];
                bl[2*nb+1][0] = t[2]; bl[2*nb+1][1] = t[3];
            }
            #pragma unroll
            for (int mi = 0; mi < 4; mi++)
                #pragma unroll
                for (int ni = 0; ni < 6; ni++) {
                    mma16816(acc[mi][ni], ah[mi], bh[ni]);
                    mma16816(acc[mi][ni], ah[mi], bl[ni]);
                    mma16816(acc[mi][ni], al[mi], bh[ni]);
                }
        }

        // all LDSMs for this stage done -> release it to the producer
        if (lane == 0) mbar_arrive(mbE + 8 * st);

        // after all hid chunks: fold deferred row-normalization scale (from smem)
        if (i == 31) {
            #pragma unroll
            for (int mi = 0; mi < 4; mi++) {
                #pragma unroll
                for (int h = 0; h < 2; h++) {
                    const float s = sScale[m0 + mi * 16 + (lane >> 2) + h * 8];
                    #pragma unroll
                    for (int ni = 0; ni < 6; ni++) {
                        acc[mi][ni][2*h]   *= s;
                        acc[mi][ni][2*h+1] *= s;
                    }
                }
            }
        }
    }

    // ---------------- epilogue: store + fused hid sum-of-squares partials
    char* dHi = g_act_hi + (size_t)(1 - buf) * ACT_BUF;
    char* dLo = g_act_lo + (size_t)(1 - buf) * ACT_BUF;
    float rowss[4][2];
    #pragma unroll
    for (int mi = 0; mi < 4; mi++) { rowss[mi][0] = 0.0f; rowss[mi][1] = 0.0f; }

    #pragma unroll
    for (int mi = 0; mi < 4; mi++) {
        const int r0 = mtile * MT + m0 + mi * 16 + (lane >> 2);
        #pragma unroll
        for (int ni = 0; ni < 6; ni++) {
            const int n = ntile * NT + n0 + ni * 8 + (lane & 3) * 2;
            const bool inHid = (n >= 1024);          // hid cols (global col >= 2048)
            #pragma unroll
            for (int h = 0; h < 2; h++) {
                const int row = r0 + h * 8;
                float v0 = fmaxf(acc[mi][ni][2*h],   0.0f);
                float v1 = fmaxf(acc[mi][ni][2*h+1], 0.0f);
                if (inHid) rowss[mi][h] += v0 * v0 + v1 * v1;
                if (last) {
                    *(float2*)(dout + (size_t)row * L_DIM + IN_DIM + n) = make_float2(v0, v1);
                } else {
                    uint32_t H, L;
                    split2(v0, v1, H, L);
                    size_t off = act_off(row, IN_DIM + n);
                    *(uint32_t*)(dHi + off) = H;
                    *(uint32_t*)(dLo + off) = L;
                }
            }
        }
    }

    if (ntile >= PART_T0) {
        // reduce within 4-lane row groups, then across the 4 N-warps via smem
        #pragma unroll
        for (int mi = 0; mi < 4; mi++)
            #pragma unroll
            for (int h = 0; h < 2; h++) {
                float v = rowss[mi][h];
                v += __shfl_xor_sync(0xFFFFFFFFu, v, 1);
                v += __shfl_xor_sync(0xFFFFFFFFu, v, 2);
                if ((lane & 3) == 0)
                    sPart[(warp & 3) * MT + m0 + mi * 16 + (lane >> 2) + h * 8] = v;
            }
        asm volatile("bar.sync 1, 256;" ::: "memory");
        if (tid < MT) {
            float p = sPart[tid] + sPart[MT + tid] + sPart[2 * MT + tid] + sPart[3 * MT + tid];
            g_part[ntile - PART_T0][mtile * MT + tid] = p;
        }
    }
}

// ---------------------------------------------------------------- final normalize
__global__ __launch_bounds__(256)
void final_norm(float* __restrict__ dout) {
    const int row = blockIdx.x, t = threadIdx.x;
    float* hid = dout + (size_t)row * L_DIM + IN_DIM + OUT_DIM;
    float4 v0 = *(float4*)(hid + t * 8);
    float4 v1 = *(float4*)(hid + t * 8 + 4);
    float ss = v0.x*v0.x + v0.y*v0.y + v0.z*v0.z + v0.w*v0.w
             + v1.x*v1.x + v1.y*v1.y + v1.z*v1.z + v1.w*v1.w;
    __shared__ float red[8];
    __shared__ float s_scale;
    #pragma unroll
    for (int off = 16; off > 0; off >>= 1) ss += __shfl_xor_sync(0xFFFFFFFFu, ss, off);
    if ((t & 31) == 0) red[t >> 5] = ss;
    __syncthreads();
    if (t == 0) {
        float tot = 0.0f;
        #pragma unroll
        for (int w = 0; w < 8; w++) tot += red[w];
        s_scale = 1.0f / fmaxf(sqrtf(tot), EPS_N);
    }
    __syncthreads();
    const float sc = s_scale;
    v0.x *= sc; v0.y *= sc; v0.z *= sc; v0.w *= sc;
    v1.x *= sc; v1.y *= sc; v1.z *= sc; v1.w *= sc;
    *(float4*)(hid + t * 8)     = v0;
    *(float4*)(hid + t * 8 + 4) = v1;
}

// ---------------------------------------------------------------- launch
extern "C" void kernel_launch(void* const* d_in, const int* in_sizes, int n_in,
                              void* d_out, int out_size) {
    const float* x = (const float*)d_in[0];
    const float* W = (const float*)d_in[2];
    const float* A = (const float*)d_in[3];
    float* out = (float*)d_out;

    cudaFuncSetAttribute(gemm_step, cudaFuncAttributeMaxDynamicSharedMemorySize, SMEM_TOT);

    prep_w<<<dim3(L_DIM / 32, NCOLS / 32), dim3(32, 32)>>>(W, A);
    init_act<<<(B_DIM * 512) / 256, 256>>>(x, out);

    for (int s = 0; s < NSTEPS; s++) {
        gemm_step<<<dim3(NTILES, MTILES), 288, SMEM_TOT>>>(out, s);
    }
    final_norm<<<B_DIM, 256>>>(out);
}

// round 15
// speedup vs baseline: 6.5698x; 1.1708x over previous
#include <cuda_runtime.h>
#include <cuda_bf16.h>
#include <stdint.h>
#include <math.h>

// ---------------------------------------------------------------- constants
#define IN_DIM   1024
#define OUT_DIM  1024
#define L_DIM    4096
#define B_DIM    1024
#define NCOLS    3072
#define NSTEPS   32
#define EPS_N    1e-12f

// GEMM: C(M=1024, N=3072). CTA 128x192, K-chunk 64.
#define MT       128
#define NT       192
#define KC       64
#define NKC      64            // total K chunks in act layout
#define NITER    48            // per-step chunks: 32 hid + 16 out (x hoisted)
#define MTILES   8
#define NTILES   16            // grid 16x8 = 128 CTAs (one wave)

#define ROWB     128           // bytes per row (64 bf16) - SW128 atom
#define ABLK     (MT*ROWB)     // 16384
#define BBLK     (NT*ROWB)     // 24576
#define STAGE    (2*ABLK + 2*BBLK)   // 81920
#define NSTG     2
#define SMEM_DATA (NSTG*STAGE)       // 163840
#define SM_MBAR   SMEM_DATA
#define SM_SSCALE (SMEM_DATA + 64)
#define SM_SPART  (SMEM_DATA + 64 + 512)
#define SMEM_TOT  (SMEM_DATA + 64 + 512 + 2048)

#define ACT_BUF  ((size_t)MTILES * NKC * ABLK)   // 8 MB per buffer
#define WT_TOT   ((size_t)NTILES * NKC * BBLK)   // 24 MB

// hid cols are n >= 1024 -> ntiles 5..15 contribute
#define PART_T0  5
#define NPART    11

// ---------------------------------------------------------------- device scratch
__device__ __align__(1024) char g_wt_hi[WT_TOT];
__device__ __align__(1024) char g_wt_lo[WT_TOT];
__device__ __align__(1024) char g_act_hi[2 * ACT_BUF];
__device__ __align__(1024) char g_act_lo[2 * ACT_BUF];
__device__ float g_part[NPART][B_DIM];                 // hid sum-of-squares partials
__device__ __align__(1024) float g_cx[(size_t)B_DIM * NCOLS];   // 12 MB: x @ mw_x^T

// ---------------------------------------------------------------- helpers
__device__ __forceinline__ uint32_t swz128(uint32_t b) { return b ^ ((b >> 3) & 0x70u); }

__device__ __forceinline__ uint32_t s2u(const void* p) {
    uint32_t a;
    asm("{ .reg .u64 t; cvta.to.shared.u64 t, %1; cvt.u32.u64 %0, t; }" : "=r"(a) : "l"(p));
    return a;
}
__device__ __forceinline__ void mbar_init(uint32_t a, uint32_t c) {
    asm volatile("mbarrier.init.shared.b64 [%0], %1;" :: "r"(a), "r"(c) : "memory");
}
__device__ __forceinline__ void mbar_expect_tx(uint32_t a, uint32_t bytes) {
    asm volatile("mbarrier.arrive.expect_tx.shared.b64 _, [%0], %1;" :: "r"(a), "r"(bytes) : "memory");
}
__device__ __forceinline__ void mbar_arrive(uint32_t a) {
    asm volatile("mbarrier.arrive.shared.b64 _, [%0];" :: "r"(a) : "memory");
}
__device__ __forceinline__ void mbar_wait(uint32_t a, uint32_t par) {
    asm volatile("{\n\t.reg .pred P;\n\tWL_%=:\n\t"
                 "mbarrier.try_wait.parity.acquire.cta.shared::cta.b64 P, [%0], %1, 0x989680;\n\t"
                 "@P bra.uni WD_%=;\n\tbra.uni WL_%=;\n\tWD_%=:\n\t}"
                 :: "r"(a), "r"(par) : "memory");
}
__device__ __forceinline__ void bulk_g2s(uint32_t dst, const void* src, uint32_t bytes, uint32_t mbar) {
    asm volatile("cp.async.bulk.shared::cluster.global.mbarrier::complete_tx::bytes [%0], [%1], %2, [%3];"
                 :: "r"(dst), "l"(src), "r"(bytes), "r"(mbar) : "memory");
}
__device__ __forceinline__ void ldsm4(uint32_t* r, uint32_t addr) {
    asm volatile("ldmatrix.sync.aligned.m8n8.x4.shared.b16 {%0,%1,%2,%3}, [%4];"
                 : "=r"(r[0]), "=r"(r[1]), "=r"(r[2]), "=r"(r[3]) : "r"(addr));
}
__device__ __forceinline__ void mma16816(float* c, const uint32_t* a, const uint32_t* b) {
    asm volatile("mma.sync.aligned.m16n8k16.row.col.f32.bf16.bf16.f32 "
                 "{%0,%1,%2,%3}, {%4,%5,%6,%7}, {%8,%9}, {%0,%1,%2,%3};"
                 : "+f"(c[0]), "+f"(c[1]), "+f"(c[2]), "+f"(c[3])
                 : "r"(a[0]), "r"(a[1]), "r"(a[2]), "r"(a[3]), "r"(b[0]), "r"(b[1]));
}

__device__ __forceinline__ void split2(float f0, float f1, uint32_t& H, uint32_t& L) {
    __nv_bfloat16 h0 = __float2bfloat16_rn(f0);
    __nv_bfloat16 h1 = __float2bfloat16_rn(f1);
    __nv_bfloat16 l0 = __float2bfloat16_rn(f0 - __bfloat162float(h0));
    __nv_bfloat16 l1 = __float2bfloat16_rn(f1 - __bfloat162float(h1));
    H = (uint32_t)__bfloat16_as_ushort(h0) | ((uint32_t)__bfloat16_as_ushort(h1) << 16);
    L = (uint32_t)__bfloat16_as_ushort(l0) | ((uint32_t)__bfloat16_as_ushort(l1) << 16);
}
__device__ __forceinline__ void split8(const float* f, uint4& H, uint4& L) {
    uint32_t hw[4], lw[4];
    #pragma unroll
    for (int p = 0; p < 4; p++) split2(f[2*p], f[2*p+1], hw[p], lw[p]);
    H = make_uint4(hw[0], hw[1], hw[2], hw[3]);
    L = make_uint4(lw[0], lw[1], lw[2], lw[3]);
}

// act tiled address: global row (0..1023), act k-index (0..4095)
__device__ __forceinline__ size_t act_off(int row, int k) {
    int mtile = row >> 7, rin = row & 127;
    int chunk = k >> 6,  cc = k & 63;
    return (size_t)(mtile * NKC + chunk) * ABLK + swz128((uint32_t)(rin * ROWB + cc * 2));
}

// ---------------------------------------------------------------- prep weights
__global__ void prep_w(const float* __restrict__ W, const float* __restrict__ A) {
    __shared__ float tile[32][33];
    const int i0 = blockIdx.y * 32, j0 = blockIdx.x * 32;
    const int tx = threadIdx.x, ty = threadIdx.y;
    tile[ty][tx] = A[(size_t)(j0 + ty) * L_DIM + (IN_DIM + i0 + tx)];
    __syncthreads();
    const int i = i0 + ty, j = j0 + tx;
    float v = W[(size_t)(IN_DIM + i) * L_DIM + j] * tile[tx][ty];
    __nv_bfloat16 h = __float2bfloat16_rn(v);
    __nv_bfloat16 l = __float2bfloat16_rn(v - __bfloat162float(h));
    const int ntile = i / NT, r = i % NT;
    const int chunk = j >> 6, cc = j & 63;
    size_t off = (size_t)(ntile * NKC + chunk) * BBLK + swz128((uint32_t)(r * ROWB + cc * 2));
    *(__nv_bfloat16*)(g_wt_hi + off) = h;
    *(__nv_bfloat16*)(g_wt_lo + off) = l;
}

// ---------------------------------------------------------------- init activations
__global__ void init_act(const float* __restrict__ x, float* __restrict__ dout) {
    int g = blockIdx.x * blockDim.x + threadIdx.x;
    if (g < NPART * B_DIM) ((float*)g_part)[g] = 0.0f;
    int row = g >> 9;
    int k0 = (g & 511) * 8;
    size_t off = act_off(row, k0);
    if (k0 < IN_DIM) {
        float4 a = *(const float4*)(x + (size_t)row * IN_DIM + k0);
        float4 b = *(const float4*)(x + (size_t)row * IN_DIM + k0 + 4);
        *(float4*)(dout + (size_t)row * L_DIM + k0)     = a;
        *(float4*)(dout + (size_t)row * L_DIM + k0 + 4) = b;
        float f[8] = {a.x, a.y, a.z, a.w, b.x, b.y, b.z, b.w};
        uint4 H, L;
        split8(f, H, L);
        *(uint4*)(g_act_hi + off) = H;
        *(uint4*)(g_act_lo + off) = L;
        *(uint4*)(g_act_hi + ACT_BUF + off) = H;
        *(uint4*)(g_act_lo + ACT_BUF + off) = L;
    } else {
        uint4 z = make_uint4(0, 0, 0, 0);
        *(uint4*)(g_act_hi + off) = z;
        *(uint4*)(g_act_lo + off) = z;
    }
}

// ---------------------------------------------------------------- shared GEMM pieces
struct FragOffs { uint32_t a[4][4]; uint32_t b[3][4]; };

__device__ __forceinline__ void make_offs(FragOffs& o, int m0, int n0, int lane) {
    #pragma unroll
    for (int mi = 0; mi < 4; mi++)
        #pragma unroll
        for (int ks = 0; ks < 4; ks++) {
            int row = m0 + mi * 16 + (lane & 15);
            int col = ks * 32 + (lane >> 4) * 16;
            o.a[mi][ks] = swz128((uint32_t)(row * ROWB + col));
        }
    #pragma unroll
    for (int nb = 0; nb < 3; nb++)
        #pragma unroll
        for (int ks = 0; ks < 4; ks++) {
            int grp = lane >> 3;
            int row = n0 + nb * 16 + ((grp & 2) << 2) + (lane & 7);
            int col = ks * 32 + (grp & 1) * 16;
            o.b[nb][ks] = swz128((uint32_t)(row * ROWB + col));
        }
}

__device__ __forceinline__ void chunk_mma(float acc[4][6][4], const FragOffs& o,
                                          uint32_t aHiB, uint32_t aLoB,
                                          uint32_t bHiB, uint32_t bLoB) {
    #pragma unroll
    for (int ks = 0; ks < 4; ks++) {
        uint32_t ah[4][4], al[4][4], bh[6][2], bl[6][2];
        #pragma unroll
        for (int mi = 0; mi < 4; mi++) {
            ldsm4(ah[mi], aHiB + o.a[mi][ks]);
            ldsm4(al[mi], aLoB + o.a[mi][ks]);
        }
        #pragma unroll
        for (int nb = 0; nb < 3; nb++) {
            uint32_t t[4];
            ldsm4(t, bHiB + o.b[nb][ks]);
            bh[2*nb][0] = t[0]; bh[2*nb][1] = t[1];
            bh[2*nb+1][0] = t[2]; bh[2*nb+1][1] = t[3];
            ldsm4(t, bLoB + o.b[nb][ks]);
            bl[2*nb][0] = t[0]; bl[2*nb][1] = t[1];
            bl[2*nb+1][0] = t[2]; bl[2*nb+1][1] = t[3];
        }
        #pragma unroll
        for (int mi = 0; mi < 4; mi++)
            #pragma unroll
            for (int ni = 0; ni < 6; ni++) {
                mma16816(acc[mi][ni], ah[mi], bh[ni]);
                mma16816(acc[mi][ni], ah[mi], bl[ni]);
                mma16816(acc[mi][ni], al[mi], bh[ni]);
            }
    }
}

// ---------------------------------------------------------------- C_x precompute
// g_cx[b][n] = sum_{k<1024} x[b,k]*mw[n,k]  (chunks 0..15 of act buffer 0)
__global__ __launch_bounds__(288, 1)
void gemm_cx(int dummy) {
    extern __shared__ __align__(1024) char smem[];
    const uint32_t sb = s2u(smem);
    const int tid = threadIdx.x, warp = tid >> 5, lane = tid & 31;
    const int ntile = blockIdx.x, mtile = blockIdx.y;

    const char* srcAh = g_act_hi + (size_t)mtile * NKC * ABLK;
    const char* srcAl = g_act_lo + (size_t)mtile * NKC * ABLK;
    const char* srcBh = g_wt_hi + (size_t)ntile * NKC * BBLK;
    const char* srcBl = g_wt_lo + (size_t)ntile * NKC * BBLK;

    const uint32_t mbF = sb + SM_MBAR;
    const uint32_t mbE = sb + SM_MBAR + 16;
    if (tid == 0) {
        mbar_init(mbF, 1); mbar_init(mbF + 8, 1);
        mbar_init(mbE, 8); mbar_init(mbE + 8, 8);
    }
    __syncthreads();

    if (warp == 8) {
        if (lane == 0) {
            for (int c = 0; c < 16; c++) {
                const int st = c & 1;
                if (c >= NSTG) mbar_wait(mbE + 8 * st, (uint32_t)(((c >> 1) - 1) & 1));
                uint32_t stB = sb + st * STAGE;
                mbar_expect_tx(mbF + 8 * st, STAGE);
                bulk_g2s(stB,                   srcAh + (size_t)c * ABLK, ABLK, mbF + 8 * st);
                bulk_g2s(stB + ABLK,            srcAl + (size_t)c * ABLK, ABLK, mbF + 8 * st);
                bulk_g2s(stB + 2 * ABLK,        srcBh + (size_t)c * BBLK, BBLK, mbF + 8 * st);
                bulk_g2s(stB + 2 * ABLK + BBLK, srcBl + (size_t)c * BBLK, BBLK, mbF + 8 * st);
            }
        }
        return;
    }

    const int m0 = (warp >> 2) * 64;
    const int n0 = (warp & 3) * 48;
    FragOffs o;
    make_offs(o, m0, n0, lane);

    float acc[4][6][4];
    #pragma unroll
    for (int mi = 0; mi < 4; mi++)
        #pragma unroll
        for (int ni = 0; ni < 6; ni++)
            #pragma unroll
            for (int q = 0; q < 4; q++) acc[mi][ni][q] = 0.0f;

    for (int i = 0; i < 16; i++) {
        const int st = i & 1;
        mbar_wait(mbF + 8 * st, (uint32_t)((i >> 1) & 1));
        const uint32_t aHiB = sb + st * STAGE;
        chunk_mma(acc, o, aHiB, aHiB + ABLK, aHiB + 2 * ABLK, aHiB + 2 * ABLK + BBLK);
        if (lane == 0) mbar_arrive(mbE + 8 * st);
    }

    #pragma unroll
    for (int mi = 0; mi < 4; mi++) {
        const int r0 = mtile * MT + m0 + mi * 16 + (lane >> 2);
        #pragma unroll
        for (int ni = 0; ni < 6; ni++) {
            const int n = ntile * NT + n0 + ni * 8 + (lane & 3) * 2;
            #pragma unroll
            for (int h = 0; h < 2; h++) {
                const int row = r0 + h * 8;
                *(float2*)(g_cx + (size_t)row * NCOLS + n) =
                    make_float2(acc[mi][ni][2*h], acc[mi][ni][2*h+1]);
            }
        }
    }
}

// ---------------------------------------------------------------- GEMM step
// 48 chunks: hid (32..63) first, fold s_row, then out (16..31); C_x added in epilogue.
__global__ __launch_bounds__(288, 1)
void gemm_step(float* __restrict__ dout, int step) {
    extern __shared__ __align__(1024) char smem[];
    const uint32_t sb = s2u(smem);
    const int tid = threadIdx.x, warp = tid >> 5, lane = tid & 31;
    const int ntile = blockIdx.x, mtile = blockIdx.y;
    const int buf = step & 1;
    const bool last = (step == NSTEPS - 1);

    const char* srcAh = g_act_hi + (size_t)buf * ACT_BUF + (size_t)mtile * NKC * ABLK;
    const char* srcAl = g_act_lo + (size_t)buf * ACT_BUF + (size_t)mtile * NKC * ABLK;
    const char* srcBh = g_wt_hi + (size_t)ntile * NKC * BBLK;
    const char* srcBl = g_wt_lo + (size_t)ntile * NKC * BBLK;

    const uint32_t mbF = sb + SM_MBAR;
    const uint32_t mbE = sb + SM_MBAR + 16;
    float* sScale = (float*)(smem + SM_SSCALE);   // [128]
    float* sPart  = (float*)(smem + SM_SPART);    // [4][128]
    if (tid == 0) {
        mbar_init(mbF, 1); mbar_init(mbF + 8, 1);
        mbar_init(mbE, 8); mbar_init(mbE + 8, 8);
    }
    __syncthreads();

    if (warp == 8) {
        if (lane == 0) {
            for (int c = 0; c < NITER; c++) {
                const int st = c & 1;
                if (c >= NSTG) mbar_wait(mbE + 8 * st, (uint32_t)(((c >> 1) - 1) & 1));
                const int ck = (c < 32) ? (32 + c) : (c - 16);   // hid, then out
                uint32_t stB = sb + st * STAGE;
                mbar_expect_tx(mbF + 8 * st, STAGE);
                bulk_g2s(stB,                   srcAh + (size_t)ck * ABLK, ABLK, mbF + 8 * st);
                bulk_g2s(stB + ABLK,            srcAl + (size_t)ck * ABLK, ABLK, mbF + 8 * st);
                bulk_g2s(stB + 2 * ABLK,        srcBh + (size_t)ck * BBLK, BBLK, mbF + 8 * st);
                bulk_g2s(stB + 2 * ABLK + BBLK, srcBl + (size_t)ck * BBLK, BBLK, mbF + 8 * st);
            }
        }
        return;
    }

    // prologue: s_row from previous-step partials
    if (tid < MT) {
        const int grow = mtile * MT + tid;
        float ss = 0.0f;
        #pragma unroll
        for (int t = 0; t < NPART; t++) ss += g_part[t][grow];
        sScale[tid] = 1.0f / fmaxf(sqrtf(ss), EPS_N);
    }
    asm volatile("bar.sync 1, 256;" ::: "memory");

    const int m0 = (warp >> 2) * 64;
    const int n0 = (warp & 3) * 48;
    FragOffs o;
    make_offs(o, m0, n0, lane);

    float acc[4][6][4];
    #pragma unroll
    for (int mi = 0; mi < 4; mi++)
        #pragma unroll
        for (int ni = 0; ni < 6; ni++)
            #pragma unroll
            for (int q = 0; q < 4; q++) acc[mi][ni][q] = 0.0f;

    for (int i = 0; i < NITER; i++) {
        const int st = i & 1;
        mbar_wait(mbF + 8 * st, (uint32_t)((i >> 1) & 1));
        const uint32_t aHiB = sb + st * STAGE;
        chunk_mma(acc, o, aHiB, aHiB + ABLK, aHiB + 2 * ABLK, aHiB + 2 * ABLK + BBLK);
        if (lane == 0) mbar_arrive(mbE + 8 * st);

        if (i == 31) {   // all hid chunks done -> fold deferred norm scale
            #pragma unroll
            for (int mi = 0; mi < 4; mi++) {
                #pragma unroll
                for (int h = 0; h < 2; h++) {
                    const float s = sScale[m0 + mi * 16 + (lane >> 2) + h * 8];
                    #pragma unroll
                    for (int ni = 0; ni < 6; ni++) {
                        acc[mi][ni][2*h]   *= s;
                        acc[mi][ni][2*h+1] *= s;
                    }
                }
            }
        }
    }

    // epilogue: add C_x, relu, store, fused hid sum-of-squares partials
    char* dHi = g_act_hi + (size_t)(1 - buf) * ACT_BUF;
    char* dLo = g_act_lo + (size_t)(1 - buf) * ACT_BUF;
    float rowss[4][2];
    #pragma unroll
    for (int mi = 0; mi < 4; mi++) { rowss[mi][0] = 0.0f; rowss[mi][1] = 0.0f; }

    #pragma unroll
    for (int mi = 0; mi < 4; mi++) {
        const int r0 = mtile * MT + m0 + mi * 16 + (lane >> 2);
        #pragma unroll
        for (int ni = 0; ni < 6; ni++) {
            const int n = ntile * NT + n0 + ni * 8 + (lane & 3) * 2;
            const bool inHid = (n >= 1024);
            #pragma unroll
            for (int h = 0; h < 2; h++) {
                const int row = r0 + h * 8;
                float2 cx = *(const float2*)(g_cx + (size_t)row * NCOLS + n);
                float v0 = fmaxf(acc[mi][ni][2*h]   + cx.x, 0.0f);
                float v1 = fmaxf(acc[mi][ni][2*h+1] + cx.y, 0.0f);
                if (inHid) rowss[mi][h] += v0 * v0 + v1 * v1;
                if (last) {
                    *(float2*)(dout + (size_t)row * L_DIM + IN_DIM + n) = make_float2(v0, v1);
                } else {
                    uint32_t H, L;
                    split2(v0, v1, H, L);
                    size_t off = act_off(row, IN_DIM + n);
                    *(uint32_t*)(dHi + off) = H;
                    *(uint32_t*)(dLo + off) = L;
                }
            }
        }
    }

    if (ntile >= PART_T0) {
        #pragma unroll
        for (int mi = 0; mi < 4; mi++)
            #pragma unroll
            for (int h = 0; h < 2; h++) {
                float v = rowss[mi][h];
                v += __shfl_xor_sync(0xFFFFFFFFu, v, 1);
                v += __shfl_xor_sync(0xFFFFFFFFu, v, 2);
                if ((lane & 3) == 0)
                    sPart[(warp & 3) * MT + m0 + mi * 16 + (lane >> 2) + h * 8] = v;
            }
        asm volatile("bar.sync 1, 256;" ::: "memory");
        if (tid < MT) {
            float p = sPart[tid] + sPart[MT + tid] + sPart[2 * MT + tid] + sPart[3 * MT + tid];
            g_part[ntile - PART_T0][mtile * MT + tid] = p;
        }
    }
}

// ---------------------------------------------------------------- final normalize
__global__ __launch_bounds__(256)
void final_norm(float* __restrict__ dout) {
    const int row = blockIdx.x, t = threadIdx.x;
    float* hid = dout + (size_t)row * L_DIM + IN_DIM + OUT_DIM;
    float4 v0 = *(float4*)(hid + t * 8);
    float4 v1 = *(float4*)(hid + t * 8 + 4);
    float ss = v0.x*v0.x + v0.y*v0.y + v0.z*v0.z + v0.w*v0.w
             + v1.x*v1.x + v1.y*v1.y + v1.z*v1.z + v1.w*v1.w;
    __shared__ float red[8];
    __shared__ float s_scale;
    #pragma unroll
    for (int off = 16; off > 0; off >>= 1) ss += __shfl_xor_sync(0xFFFFFFFFu, ss, off);
    if ((t & 31) == 0) red[t >> 5] = ss;
    __syncthreads();
    if (t == 0) {
        float tot = 0.0f;
        #pragma unroll
        for (int w = 0; w < 8; w++) tot += red[w];
        s_scale = 1.0f / fmaxf(sqrtf(tot), EPS_N);
    }
    __syncthreads();
    const float sc = s_scale;
    v0.x *= sc; v0.y *= sc; v0.z *= sc; v0.w *= sc;
    v1.x *= sc; v1.y *= sc; v1.z *= sc; v1.w *= sc;
    *(float4*)(hid + t * 8)     = v0;
    *(float4*)(hid + t * 8 + 4) = v1;
}

// ---------------------------------------------------------------- launch
extern "C" void kernel_launch(void* const* d_in, const int* in_sizes, int n_in,
                              void* d_out, int out_size) {
    const float* x = (const float*)d_in[0];
    const float* W = (const float*)d_in[2];
    const float* A = (const float*)d_in[3];
    float* out = (float*)d_out;

    cudaFuncSetAttribute(gemm_cx,   cudaFuncAttributeMaxDynamicSharedMemorySize, SMEM_TOT);
    cudaFuncSetAttribute(gemm_step, cudaFuncAttributeMaxDynamicSharedMemorySize, SMEM_TOT);

    prep_w<<<dim3(L_DIM / 32, NCOLS / 32), dim3(32, 32)>>>(W, A);
    init_act<<<(B_DIM * 512) / 256, 256>>>(x, out);
    gemm_cx<<<dim3(NTILES, MTILES), 288, SMEM_TOT>>>(0);

    for (int s = 0; s < NSTEPS; s++) {
        gemm_step<<<dim3(NTILES, MTILES), 288, SMEM_TOT>>>(out, s);
    }
    final_norm<<<B_DIM, 256>>>(out);
}